// round 11
// baseline (speedup 1.0000x reference)
#include <cuda_runtime.h>
#include <cstdint>

#define NN 100000
#define NE 300000
#define HID 256

// ---- scratch (static device globals; allocation-free) ----
__device__ float g_h0[NN * HID];
__device__ float g_h1[NN * HID];
__device__ float g_ta[NN * HID];              // t ping buffer
__device__ float g_tb[NN * HID];              // t pong buffer
__device__ float g_uv[NN * HID];              // [U | V] = h_final @ [W1top|W1bot]
__device__ int   g_atype[NN];
__device__ int   g_pv[NN];
__device__ float g_deg[NN];
__device__ int   g_cnt[NN];
__device__ int   g_rowptr[NN + 1];
__device__ int   g_cur[NN];
__device__ int   g_ecol[NE];                  // CSR-slot -> source node
__device__ int   g_ebt[NE];                   // CSR-slot -> bond type
__device__ int   g_bsum[98];
__device__ int   g_boff[98];
__device__ float g_tlogits[11 * 8];
__device__ int   g_tpv[11];
__device__ float g_msgbias[3 * 5 * 256];      // folded bond-emb @ Wmsg[256:] + bmsg
__device__ float g_wmsg_tf[3 * 256 * 256];    // pre-rounded tf32 weights
__device__ float g_wself_tf[3 * 256 * 256];
__device__ float g_bcwcat_tf[256 * 256];      // [W1top | W1bot] concatenated, tf32

__device__ __forceinline__ float f2tff(float x) {
    unsigned r;
    asm("cvt.rna.tf32.f32 %0, %1;" : "=r"(r) : "f"(x));
    return __uint_as_float(r);
}
__device__ __forceinline__ float4 f2tff4(float4 v) {
    v.x = f2tff(v.x); v.y = f2tff(v.y); v.z = f2tff(v.z); v.w = f2tff(v.w);
    return v;
}

__device__ __forceinline__ void mma_tf32(float c[4],
    unsigned a0, unsigned a1, unsigned a2, unsigned a3,
    unsigned b0, unsigned b1)
{
    asm volatile(
        "mma.sync.aligned.m16n8k8.row.col.f32.tf32.tf32.f32 "
        "{%0,%1,%2,%3}, {%4,%5,%6,%7}, {%8,%9}, {%0,%1,%2,%3};"
        : "+f"(c[0]), "+f"(c[1]), "+f"(c[2]), "+f"(c[3])
        : "r"(a0), "r"(a1), "r"(a2), "r"(a3), "r"(b0), "r"(b1));
}

__device__ __forceinline__ void cpasync16(void* sptr, const void* g) {
    uint32_t sa = (uint32_t)__cvta_generic_to_shared(sptr);
    asm volatile("cp.async.cg.shared.global [%0], [%1], 16;" :: "r"(sa), "l"(g) : "memory");
}

// Pipelined 32xK x Kx256 tf32 mainloop. As: [32][36], WsA/WsB: [32][264].
// NOTE: no __restrict__ on hin — selfagg re-reads rows it wrote pre-barrier.
__device__ __forceinline__ void gemm_mainloop(
    float c[2][4][4], const float* hin, const float* __restrict__ wtf,
    int nb, int ksteps, float (*As)[36], float (*WsA)[264], float (*WsB)[264])
{
    int tid = threadIdx.x;
    int warp = tid >> 5, lane = tid & 31;
    int n0 = warp * 32;
    const int lr = lane >> 2, lc = lane & 3;
    const int arow = tid >> 3, ac4 = (tid & 7) * 4;

    // prologue: W tile 0 async into WsA; A tile 0 into registers
    float4 aNext = *(const float4*)&hin[(size_t)(nb + arow) * HID + ac4];
#pragma unroll
    for (int i = 0; i < 8; i++) {
        int idx = tid + 256 * i;
        int k = idx >> 6, c4 = (idx & 63) * 4;
        cpasync16(&WsA[k][c4], &wtf[(size_t)k * HID + c4]);
    }
    asm volatile("cp.async.commit_group;" ::: "memory");

    for (int kt = 0; kt < ksteps; kt++) {
        float (*Wcur)[264] = (kt & 1) ? WsB : WsA;
        float (*Wnxt)[264] = (kt & 1) ? WsA : WsB;
        float4 aCur = aNext;
        __syncthreads();                       // prev compute done: safe to touch As/Wnxt
        bool next = (kt + 1 < ksteps);
        if (next) {
            int k0n = (kt + 1) * 32;
#pragma unroll
            for (int i = 0; i < 8; i++) {
                int idx = tid + 256 * i;
                int k = idx >> 6, c4 = (idx & 63) * 4;
                cpasync16(&Wnxt[k][c4], &wtf[(size_t)(k0n + k) * HID + c4]);
            }
            asm volatile("cp.async.commit_group;" ::: "memory");
            aNext = *(const float4*)&hin[(size_t)(nb + arow) * HID + k0n + ac4];
        }
        *(float4*)&As[arow][ac4] = f2tff4(aCur);
        if (next) asm volatile("cp.async.wait_group 1;" ::: "memory");
        else      asm volatile("cp.async.wait_group 0;" ::: "memory");
        __syncthreads();
#pragma unroll
        for (int ks = 0; ks < 4; ks++) {
            int kk = ks * 8;
            unsigned b[4][2];
#pragma unroll
            for (int n = 0; n < 4; n++) {
                int nc = n0 + n * 8 + lr;
                b[n][0] = __float_as_uint(Wcur[kk + lc][nc]);
                b[n][1] = __float_as_uint(Wcur[kk + 4 + lc][nc]);
            }
#pragma unroll
            for (int m = 0; m < 2; m++) {
                int r = m * 16 + lr;
                unsigned a0 = __float_as_uint(As[r][kk + lc]);
                unsigned a1 = __float_as_uint(As[r + 8][kk + lc]);
                unsigned a2 = __float_as_uint(As[r][kk + 4 + lc]);
                unsigned a3 = __float_as_uint(As[r + 8][kk + 4 + lc]);
#pragma unroll
                for (int n = 0; n < 4; n++)
                    mma_tf32(c[m][n], a0, a1, a2, a3, b[n][0], b[n][1]);
            }
        }
    }
}

#define SMEM_PIPE ((32 * 36 + 2 * 32 * 264) * 4)

// ============================================================
// Prep: type-pred MLP, bond-bias fold, tf32 weight pre-round
// (wmsg top / wself / bc_w1 concat), zero counts
// ============================================================
__global__ void k_prep(const float* __restrict__ atom_emb,
                       const float* __restrict__ vp_w1, const float* __restrict__ vp_b1,
                       const float* __restrict__ vp_w2, const float* __restrict__ vp_b2,
                       const float* __restrict__ wmsg, const float* __restrict__ bmsg,
                       const float* __restrict__ bond_emb,
                       const float* __restrict__ wself, const float* __restrict__ bcw1)
{
    int b = blockIdx.x;
    int tid = threadIdx.x;
    if (b == 0) {
        if (tid >= 11) return;
        int t = tid;
        float z[32];
        for (int j = 0; j < 32; j++) {
            float s = vp_b1[j];
            for (int k = 0; k < 64; k++) s += atom_emb[t * 64 + k] * vp_w1[k * 32 + j];
            z[j] = fmaxf(s, 0.f);
        }
        float best = -1e30f; int bi = 0;
        for (int j = 0; j < 8; j++) {
            float s = vp_b2[j];
            for (int k = 0; k < 32; k++) s += z[k] * vp_w2[k * 8 + j];
            g_tlogits[t * 8 + j] = s;
            if (s > best) { best = s; bi = j; }
        }
        g_tpv[t] = bi + 1;
    } else if (b < 16) {
        int idx = b - 1;
        int l = idx / 5, bt = idx % 5;
        const float* w = wmsg + (size_t)l * 320 * HID;
        float s = bmsg[l * HID + tid];
#pragma unroll 8
        for (int j = 0; j < 64; j++)
            s += bond_emb[bt * 64 + j] * w[(size_t)(256 + j) * HID + tid];
        g_msgbias[(size_t)idx * 256 + tid] = s;
    } else if (b < 16 + 768) {
        int i = (b - 16) * 256 + tid;        // over 3*65536
        int l = i >> 16, rest = i & 65535;
        g_wmsg_tf[i] = f2tff(wmsg[(size_t)l * 320 * 256 + rest]);
    } else if (b < 16 + 1536) {
        int i = (b - 784) * 256 + tid;
        g_wself_tf[i] = f2tff(wself[i]);
    } else if (b < 16 + 1792) {
        int i = (b - 1552) * 256 + tid;      // over 256*256
        int k = i >> 8, n = i & 255;
        float v = (n < 128) ? bcw1[(size_t)k * 128 + n]
                            : bcw1[(size_t)(256 + k) * 128 + (n - 128)];
        g_bcwcat_tf[i] = f2tff(v);
    } else {
        int i = (b - 1808) * 256 + tid;
        if (i < NN) g_cnt[i] = 0;
    }
}

// ============================================================
// Node init
// ============================================================
__global__ void k_node_init(const float* __restrict__ x,
                            const float* __restrict__ atom_emb,
                            float* __restrict__ out_vlog)
{
    int gid = blockIdx.x * blockDim.x + threadIdx.x;
    int n = gid >> 5, lane = gid & 31;
    if (n >= NN) return;
    int at = (int)x[(size_t)n * 16];
    at = min(max(at, 0), 10);
    int pv = g_tpv[at];
    if (lane == 0) { g_atype[n] = at; g_pv[n] = pv; }
    if (lane < 8) out_vlog[(size_t)n * 8 + lane] = g_tlogits[at * 8 + lane];
#pragma unroll
    for (int r = 0; r < 8; r++) {
        int c = lane + 32 * r;
        float v;
        if (c < 64)      v = atom_emb[at * 64 + c];
        else if (c < 72) v = (c - 64 == pv - 1) ? 1.f : 0.f;
        else             v = 0.f;
        g_h0[(size_t)n * HID + c] = v;
    }
}

// ============================================================
// CSR build: count -> 3-phase parallel scan (+viol output) -> scatter
// ============================================================
__global__ void k_count(const int* __restrict__ edge_index)
{
    int e = blockIdx.x * blockDim.x + threadIdx.x;
    if (e < NE) atomicAdd(&g_cnt[edge_index[e]], 1);
}

__global__ void k_scan1()
{
    __shared__ int sh[32];
    int t = threadIdx.x;
    int n = blockIdx.x * 1024 + t;
    int c = (n < NN) ? g_cnt[n] : 0;
#pragma unroll
    for (int o = 16; o > 0; o >>= 1) c += __shfl_down_sync(0xffffffffu, c, o);
    if ((t & 31) == 0) sh[t >> 5] = c;
    __syncthreads();
    if (t < 32) {
        int v = sh[t];
#pragma unroll
        for (int o = 16; o > 0; o >>= 1) v += __shfl_down_sync(0xffffffffu, v, o);
        if (t == 0) g_bsum[blockIdx.x] = v;
    }
}

__global__ void k_scan2()
{
    __shared__ int sh[128];
    int t = threadIdx.x;
    int v = (t < 98) ? g_bsum[t] : 0;
    sh[t] = v;
    __syncthreads();
    for (int off = 1; off < 128; off <<= 1) {
        int u = (t >= off) ? sh[t - off] : 0;
        __syncthreads();
        sh[t] += u;
        __syncthreads();
    }
    if (t < 98) g_boff[t] = sh[t] - v;
    if (t == 97) g_rowptr[NN] = sh[97];
}

__global__ void k_scan3(float* __restrict__ out_viol)
{
    __shared__ int sh[1024];
    int t = threadIdx.x;
    int n = blockIdx.x * 1024 + t;
    int c = (n < NN) ? g_cnt[n] : 0;
    sh[t] = c;
    __syncthreads();
    for (int off = 1; off < 1024; off <<= 1) {
        int u = (t >= off) ? sh[t - off] : 0;
        __syncthreads();
        sh[t] += u;
        __syncthreads();
    }
    if (n < NN) {
        int excl = sh[t] - c + g_boff[blockIdx.x];
        g_rowptr[n] = excl;
        g_cur[n] = excl;
        g_deg[n] = (float)c;
        out_viol[n] = fmaxf((float)c - (float)g_pv[n], 0.f);
    }
}

__global__ void k_scatter(const int* __restrict__ edge_index,
                          const float* __restrict__ edge_attr)
{
    int e = blockIdx.x * blockDim.x + threadIdx.x;
    if (e < NE) {
        int pos = atomicAdd(&g_cur[edge_index[e]], 1);
        g_ecol[pos] = edge_index[NE + e];
        g_ebt[pos] = min(max((int)edge_attr[(size_t)e * 4], 0), 4);
    }
}

// ============================================================
// Generic node GEMM (pipelined): out = hin @ wtf, [32 x 256]
// (used only for layer-0 t)
// ============================================================
__global__ __launch_bounds__(256, 3) void k_gemm(const float* __restrict__ hin,
        const float* __restrict__ wtf, float* __restrict__ outp, int ksteps)
{
    extern __shared__ float sm[];
    float (*As)[36] = (float(*)[36])sm;
    float (*WsA)[264] = (float(*)[264])(sm + 32 * 36);
    float (*WsB)[264] = (float(*)[264])(sm + 32 * 36 + 32 * 264);
    int tid = threadIdx.x;
    int nb = blockIdx.x * 32;
    int warp = tid >> 5, lane = tid & 31;
    int n0 = warp * 32;
    float c[2][4][4];
#pragma unroll
    for (int m = 0; m < 2; m++)
#pragma unroll
        for (int n = 0; n < 4; n++)
#pragma unroll
            for (int j = 0; j < 4; j++) c[m][n][j] = 0.f;

    gemm_mainloop(c, hin, wtf, nb, ksteps, As, WsA, WsB);

    int g = lane >> 2, cc = 2 * (lane & 3);
#pragma unroll
    for (int m = 0; m < 2; m++) {
        int row0 = nb + m * 16 + g;
        int row1 = row0 + 8;
#pragma unroll
        for (int n = 0; n < 4; n++) {
            int col = n0 + n * 8 + cc;
            *(float2*)&outp[(size_t)row0 * HID + col] = make_float2(c[m][n][0], c[m][n][1]);
            *(float2*)&outp[(size_t)row1 * HID + col] = make_float2(c[m][n][2], c[m][n][3]);
        }
    }
}

// ============================================================
// self GEMM + aggregation + FUSED next GEMM:
// h_new = relu(h @ Wself + b + sum_in relu(tcur[col] + msgbias[bt]))
// then outnext = h_new @ wnext  (written to a DIFFERENT t buffer /
// g_uv — never the buffer other blocks are still gathering from).
// Last layer fuses valence damping, writes out_h.
// ============================================================
__global__ __launch_bounds__(256, 3) void k_selfagg(int ping, int ksteps, int l,
        const float* __restrict__ bself, int damp, float* __restrict__ out_h,
        const float* __restrict__ tcur,
        const float* __restrict__ wnext, float* __restrict__ outnext)
{
    extern __shared__ float sm[];
    float (*As)[36] = (float(*)[36])sm;
    float (*WsA)[264] = (float(*)[264])(sm + 32 * 36);
    float (*WsB)[264] = (float(*)[264])(sm + 32 * 36 + 32 * 264);
    const float* hin         = ping ? g_h1 : g_h0;
    float* __restrict__ hout = damp ? out_h : (ping ? g_h0 : g_h1);
    const float* __restrict__ wtf = g_wself_tf + (size_t)l * 65536;
    int tid = threadIdx.x;
    int nb = blockIdx.x * 32;
    int warp = tid >> 5, lane = tid & 31;
    int n0 = warp * 32;
    float c[2][4][4];
#pragma unroll
    for (int m = 0; m < 2; m++)
#pragma unroll
        for (int n = 0; n < 4; n++)
#pragma unroll
            for (int j = 0; j < 4; j++) c[m][n][j] = 0.f;

    gemm_mainloop(c, hin, wtf, nb, ksteps, As, WsA, WsB);

    // stage msgbias[l] (5x256) into shared (reuse WsA region)
    __syncthreads();
    float* smb = sm + 32 * 36;
    {
        const float* mb = g_msgbias + (size_t)l * 1280;
#pragma unroll
        for (int i = 0; i < 5; i++) smb[tid + 256 * i] = mb[tid + 256 * i];
    }
    __syncthreads();

    int g = lane >> 2, cc = 2 * (lane & 3);
#pragma unroll
    for (int m = 0; m < 2; m++) {
        int row0 = nb + m * 16 + g;
        int row1 = row0 + 8;
        int s0 = __ldg(&g_rowptr[row0]), e0 = __ldg(&g_rowptr[row0 + 1]);
        for (int j = s0; j < e0; j++) {
            const float* tr = &tcur[(size_t)__ldg(&g_ecol[j]) * HID];
            const float* mb = smb + __ldg(&g_ebt[j]) * 256;
#pragma unroll
            for (int n = 0; n < 4; n++) {
                int col = n0 + n * 8 + cc;
                float2 v = *(const float2*)&tr[col];
                c[m][n][0] += fmaxf(v.x + mb[col],     0.f);
                c[m][n][1] += fmaxf(v.y + mb[col + 1], 0.f);
            }
        }
        int s1 = __ldg(&g_rowptr[row1]), e1 = __ldg(&g_rowptr[row1 + 1]);
        for (int j = s1; j < e1; j++) {
            const float* tr = &tcur[(size_t)__ldg(&g_ecol[j]) * HID];
            const float* mb = smb + __ldg(&g_ebt[j]) * 256;
#pragma unroll
            for (int n = 0; n < 4; n++) {
                int col = n0 + n * 8 + cc;
                float2 v = *(const float2*)&tr[col];
                c[m][n][2] += fmaxf(v.x + mb[col],     0.f);
                c[m][n][3] += fmaxf(v.y + mb[col + 1], 0.f);
            }
        }
        float sc0 = 1.f, sc1 = 1.f;
        if (damp) {
            sc0 = 1.f / (1.f + fmaxf((float)(e0 - s0) - (float)g_pv[row0], 0.f));
            sc1 = 1.f / (1.f + fmaxf((float)(e1 - s1) - (float)g_pv[row1], 0.f));
        }
#pragma unroll
        for (int n = 0; n < 4; n++) {
            int col = n0 + n * 8 + cc;
            float b0 = __ldg(&bself[col]), b1 = __ldg(&bself[col + 1]);
            float2 r0, r1;
            r0.x = fmaxf(c[m][n][0] + b0, 0.f) * sc0;
            r0.y = fmaxf(c[m][n][1] + b1, 0.f) * sc0;
            r1.x = fmaxf(c[m][n][2] + b0, 0.f) * sc1;
            r1.y = fmaxf(c[m][n][3] + b1, 0.f) * sc1;
            *(float2*)&hout[(size_t)row0 * HID + col] = r0;
            *(float2*)&hout[(size_t)row1 * HID + col] = r1;
        }
    }

    // ---- fused next GEMM: outnext = hout(tile) @ wnext ----
    // outnext is a DISJOINT buffer from tcur, so no cross-block hazard.
    __syncthreads();   // h writes visible block-wide; smb reads done
    float c2[2][4][4];
#pragma unroll
    for (int m = 0; m < 2; m++)
#pragma unroll
        for (int n = 0; n < 4; n++)
#pragma unroll
            for (int j = 0; j < 4; j++) c2[m][n][j] = 0.f;

    gemm_mainloop(c2, hout, wnext, nb, 8, As, WsA, WsB);

#pragma unroll
    for (int m = 0; m < 2; m++) {
        int row0 = nb + m * 16 + g;
        int row1 = row0 + 8;
#pragma unroll
        for (int n = 0; n < 4; n++) {
            int col = n0 + n * 8 + cc;
            *(float2*)&outnext[(size_t)row0 * HID + col] = make_float2(c2[m][n][0], c2[m][n][1]);
            *(float2*)&outnext[(size_t)row1 * HID + col] = make_float2(c2[m][n][2], c2[m][n][3]);
        }
    }
}

// ============================================================
// Bond head: stage1 = gather relu(U[row]+V[col]+pv terms+b1),
// stages 2-3 SIMT. No MMA here.
// ============================================================
__global__ __launch_bounds__(256) void k_bc(
        const float* __restrict__ w1, const float* __restrict__ b1,
        const float* __restrict__ w2, const float* __restrict__ b2,
        const float* __restrict__ w3, const float* __restrict__ b3,
        const int* __restrict__ edge_index, float* __restrict__ out_bl)
{
    __shared__ float T1[32][132];
    __shared__ float T2[32][65];
    __shared__ float Ws[32][68];
    __shared__ float s_wpr[128], s_wpc[128], s_bb[128];
    __shared__ int s_row[32], s_col[32], s_atr[32], s_atc[32];
    __shared__ float s_pvr[32], s_pvc[32];
    int tid = threadIdx.x;
    int eb = blockIdx.x * 32;
    if (tid < 32) {
        int e = eb + tid;
        int r = edge_index[e], c = edge_index[NE + e];
        s_row[tid] = r; s_col[tid] = c;
        s_pvr[tid] = (float)g_pv[r]; s_pvc[tid] = (float)g_pv[c];
        s_atr[tid] = g_atype[r];     s_atc[tid] = g_atype[c];
    }
    if (tid < 128) {
        s_wpr[tid] = w1[512 * 128 + tid];
        s_wpc[tid] = w1[513 * 128 + tid];
        s_bb[tid]  = b1[tid];
    }
    __syncthreads();

    // ---- stage 1: gather [32 x 128] from g_uv ----
    int warp = tid >> 5, lane = tid & 31;
    int o = lane * 4;
#pragma unroll
    for (int it = 0; it < 4; it++) {
        int e = warp * 4 + it;
        float4 u = *(const float4*)&g_uv[(size_t)s_row[e] * 256 + o];
        float4 v = *(const float4*)&g_uv[(size_t)s_col[e] * 256 + 128 + o];
        float pr = s_pvr[e], pc = s_pvc[e];
        float4 t;
        t.x = fmaxf(u.x + v.x + pr * s_wpr[o]     + pc * s_wpc[o]     + s_bb[o],     0.f);
        t.y = fmaxf(u.y + v.y + pr * s_wpr[o + 1] + pc * s_wpc[o + 1] + s_bb[o + 1], 0.f);
        t.z = fmaxf(u.z + v.z + pr * s_wpr[o + 2] + pc * s_wpc[o + 2] + s_bb[o + 2], 0.f);
        t.w = fmaxf(u.w + v.w + pr * s_wpr[o + 3] + pc * s_wpc[o + 3] + s_bb[o + 3], 0.f);
        *(float4*)&T1[e][o] = t;
    }
    __syncthreads();

    // ---- stage 2: [32 x 64], K=128 (SIMT) ----
    float acc2[2][4];
#pragma unroll
    for (int i = 0; i < 2; i++)
#pragma unroll
        for (int j = 0; j < 4; j++) acc2[i][j] = 0.f;
    const int tx2 = tid & 15, ty2 = tid >> 4;
    for (int kt = 0; kt < 4; kt++) {
        int k0 = kt * 32;
#pragma unroll
        for (int i = 0; i < 2; i++) {
            int idx = tid + 256 * i;
            int k = idx >> 4, c4 = (idx & 15) * 4;
            *(float4*)&Ws[k][c4] = *(const float4*)&w2[(size_t)(k0 + k) * 64 + c4];
        }
        __syncthreads();
#pragma unroll
        for (int kk = 0; kk < 32; kk++) {
            float a0 = T1[ty2 * 2][k0 + kk];
            float a1 = T1[ty2 * 2 + 1][k0 + kk];
            float4 w = *(const float4*)&Ws[kk][tx2 * 4];
            acc2[0][0] += a0 * w.x; acc2[0][1] += a0 * w.y;
            acc2[0][2] += a0 * w.z; acc2[0][3] += a0 * w.w;
            acc2[1][0] += a1 * w.x; acc2[1][1] += a1 * w.y;
            acc2[1][2] += a1 * w.z; acc2[1][3] += a1 * w.w;
        }
        __syncthreads();
    }
#pragma unroll
    for (int i = 0; i < 2; i++) {
        int e = ty2 * 2 + i;
#pragma unroll
        for (int j = 0; j < 4; j++) {
            int oo = tx2 * 4 + j;
            T2[e][oo] = fmaxf(acc2[i][j] + __ldg(&b2[oo]), 0.f);
        }
    }
    __syncthreads();

    // ---- stage 3: [32 x 4], K=64, + chemical penalties ----
    if (tid < 128) {
        int e = tid >> 2, oo = tid & 3;
        float s = __ldg(&b3[oo]);
#pragma unroll
        for (int k = 0; k < 64; k++) s += T2[e][k] * __ldg(&w3[k * 4 + oo]);
        int ar = s_atr[e], ac = s_atc[e];
        float pr = s_pvr[e], pc = s_pvc[e];
        bool hal = (ar == 4) || (ar == 5) || (ac == 4) || (ac == 5);
        bool l1 = (pr <= 1.f) || (pc <= 1.f);
        bool l2 = (pr <= 2.f) || (pc <= 2.f);
        float pen = 0.f;
        if (oo >= 1) { if (hal) pen -= 100.f; if (l1) pen -= 50.f; }
        if (oo == 2) { if (l2) pen -= 50.f; }
        out_bl[(size_t)(eb + e) * 4 + oo] = s + pen;
    }
}

// ============================================================
// Chem head (SIMT; small)
// ============================================================
__global__ __launch_bounds__(256) void k_cp(const float* __restrict__ hfin,
        const float* __restrict__ w1, const float* __restrict__ b1,
        const float* __restrict__ w2, const float* __restrict__ b2,
        float* __restrict__ out_cp)
{
    __shared__ float As[32][36];
    __shared__ float Ws[32][132];
    __shared__ float T1[32][129];
    int tid = threadIdx.x;
    int nb = blockIdx.x * 32;
    float acc[4][4];
#pragma unroll
    for (int i = 0; i < 4; i++)
#pragma unroll
        for (int j = 0; j < 4; j++) acc[i][j] = 0.f;
    const int tx = tid & 31, ty = tid >> 5;
    const int arow = tid >> 3, ac4 = (tid & 7) * 4;
    for (int kt = 0; kt < 8; kt++) {
        int k0 = kt * 32;
        *(float4*)&As[arow][ac4] =
            *(const float4*)&hfin[(size_t)(nb + arow) * HID + k0 + ac4];
#pragma unroll
        for (int i = 0; i < 4; i++) {
            int idx = tid + 256 * i;
            int k = idx >> 5, c4 = (idx & 31) * 4;
            *(float4*)&Ws[k][c4] = *(const float4*)&w1[(size_t)(k0 + k) * 128 + c4];
        }
        __syncthreads();
#pragma unroll
        for (int kk = 0; kk < 32; kk++) {
            float a[4];
#pragma unroll
            for (int i = 0; i < 4; i++) a[i] = As[ty * 4 + i][kk];
            float4 w = *(const float4*)&Ws[kk][tx * 4];
#pragma unroll
            for (int i = 0; i < 4; i++) {
                acc[i][0] += a[i] * w.x; acc[i][1] += a[i] * w.y;
                acc[i][2] += a[i] * w.z; acc[i][3] += a[i] * w.w;
            }
        }
        __syncthreads();
    }
#pragma unroll
    for (int i = 0; i < 4; i++) {
        int e = ty * 4 + i;
#pragma unroll
        for (int j = 0; j < 4; j++) {
            int o = tx * 4 + j;
            T1[e][o] = fmaxf(acc[i][j] + __ldg(&b1[o]), 0.f);
        }
    }
    __syncthreads();

    float acc2[4] = {0.f, 0.f, 0.f, 0.f};
    const int tx2 = tid & 7, ty2 = tid >> 3;
    for (int kt = 0; kt < 4; kt++) {
        int k0 = kt * 32;
        {
            int k = tid >> 3, c4 = (tid & 7) * 4;
            *(float4*)&Ws[k][c4] = *(const float4*)&w2[(size_t)(k0 + k) * 32 + c4];
        }
        __syncthreads();
#pragma unroll
        for (int kk = 0; kk < 32; kk++) {
            float a = T1[ty2][k0 + kk];
            float4 w = *(const float4*)&Ws[kk][tx2 * 4];
            acc2[0] += a * w.x; acc2[1] += a * w.y;
            acc2[2] += a * w.z; acc2[3] += a * w.w;
        }
        __syncthreads();
    }
#pragma unroll
    for (int j = 0; j < 4; j++) {
        int o = tx2 * 4 + j;
        out_cp[(size_t)(nb + ty2) * 32 + o] = acc2[j] + __ldg(&b2[o]);
    }
}

// ============================================================
extern "C" void kernel_launch(void* const* d_in, const int* in_sizes, int n_in,
                              void* d_out, int out_size)
{
    (void)in_sizes; (void)n_in; (void)out_size;
    const float* x         = (const float*)d_in[0];
    const float* edge_attr = (const float*)d_in[1];
    const float* atom_emb  = (const float*)d_in[2];
    const float* bond_emb  = (const float*)d_in[3];
    const float* vp_w1     = (const float*)d_in[4];
    const float* vp_b1     = (const float*)d_in[5];
    const float* vp_w2     = (const float*)d_in[6];
    const float* vp_b2     = (const float*)d_in[7];
    const float* gnn_wself = (const float*)d_in[8];
    const float* gnn_bself = (const float*)d_in[9];
    const float* gnn_wmsg  = (const float*)d_in[10];
    const float* gnn_bmsg  = (const float*)d_in[11];
    const float* bc_w1     = (const float*)d_in[12];
    const float* bc_b1     = (const float*)d_in[13];
    const float* bc_w2     = (const float*)d_in[14];
    const float* bc_b2     = (const float*)d_in[15];
    const float* bc_w3     = (const float*)d_in[16];
    const float* bc_b3     = (const float*)d_in[17];
    const float* cp_w1     = (const float*)d_in[18];
    const float* cp_b1     = (const float*)d_in[19];
    const float* cp_w2     = (const float*)d_in[20];
    const float* cp_b2     = (const float*)d_in[21];
    const int* edge_index  = (const int*)d_in[22];

    float* out      = (float*)d_out;
    float* out_h    = out;                                 // [N,256]
    float* out_cp   = out_h    + (size_t)NN * HID;         // [N,32]
    float* out_vlog = out_cp   + (size_t)NN * 32;          // [N,8]
    float* out_bl   = out_vlog + (size_t)NN * 8;           // [E,4]
    float* out_viol = out_bl   + (size_t)NE * 4;           // [N]

    cudaFuncSetAttribute(k_gemm, cudaFuncAttributeMaxDynamicSharedMemorySize, SMEM_PIPE);
    cudaFuncSetAttribute(k_selfagg, cudaFuncAttributeMaxDynamicSharedMemorySize, SMEM_PIPE);

    // resolve device-global addresses
    float *p_h0, *p_ta, *p_tb, *p_uv, *p_wmsg, *p_bccat;
    cudaGetSymbolAddress((void**)&p_h0,    g_h0);
    cudaGetSymbolAddress((void**)&p_ta,    g_ta);
    cudaGetSymbolAddress((void**)&p_tb,    g_tb);
    cudaGetSymbolAddress((void**)&p_uv,    g_uv);
    cudaGetSymbolAddress((void**)&p_wmsg,  g_wmsg_tf);
    cudaGetSymbolAddress((void**)&p_bccat, g_bcwcat_tf);

    k_prep<<<2199, 256>>>(atom_emb, vp_w1, vp_b1, vp_w2, vp_b2,
                          gnn_wmsg, gnn_bmsg, bond_emb, gnn_wself, bc_w1);
    k_node_init<<<(NN * 32 + 255) / 256, 256>>>(x, atom_emb, out_vlog);
    k_count<<<(NE + 255) / 256, 256>>>(edge_index);
    k_gemm<<<NN / 32, 256, SMEM_PIPE>>>(p_h0, p_wmsg, p_ta, 3);  // layer-0 t (captured)
    k_scan1<<<98, 1024>>>();
    k_scan2<<<1, 128>>>();
    k_scan3<<<98, 1024>>>(out_viol);
    k_scatter<<<(NE + 255) / 256, 256>>>(edge_index, edge_attr);

    // layer 0: self+agg (h0 -> h1) reading g_ta; fused t1 -> g_tb
    k_selfagg<<<NN / 32, 256, SMEM_PIPE>>>(0, 3, 0, gnn_bself + 0 * HID, 0, out_h,
                                           p_ta, p_wmsg + 65536, p_tb);
    // layer 1: (h1 -> h0) reading g_tb; fused t2 -> g_ta
    k_selfagg<<<NN / 32, 256, SMEM_PIPE>>>(1, 8, 1, gnn_bself + 1 * HID, 0, out_h,
                                           p_tb, p_wmsg + 2 * 65536, p_ta);
    // layer 2: (h0 -> out_h, damped) reading g_ta; fused uv -> g_uv
    k_selfagg<<<NN / 32, 256, SMEM_PIPE>>>(0, 8, 2, gnn_bself + 2 * HID, 1, out_h,
                                           p_ta, p_bccat, p_uv);

    k_bc<<<NE / 32, 256>>>(bc_w1, bc_b1, bc_w2, bc_b2, bc_w3, bc_b3,
                           edge_index, out_bl);
    k_cp<<<NN / 32, 256>>>(out_h, cp_w1, cp_b1, cp_w2, cp_b2, out_cp);
}

// round 12
// speedup vs baseline: 1.4676x; 1.4676x over previous
#include <cuda_runtime.h>
#include <cstdint>

#define NN 100000
#define NE 300000
#define HID 256

// ---- scratch (static device globals; allocation-free) ----
__device__ float g_h0[NN * HID];
__device__ float g_h1[NN * HID];
__device__ float g_t[NN * HID];               // t = h @ Wmsg_top (per node)
__device__ float g_uv[NN * HID];              // [U | V] = h_final @ [W1top|W1bot]
__device__ int   g_atype[NN];
__device__ int   g_pv[NN];
__device__ float g_deg[NN];
__device__ int   g_cnt[NN];
__device__ int   g_rowptr[NN + 1];
__device__ int   g_cur[NN];
__device__ int   g_ecol[NE];                  // CSR-slot -> source node
__device__ int   g_ebt[NE];                   // CSR-slot -> bond type
__device__ int   g_bsum[98];
__device__ int   g_boff[98];
__device__ float g_tlogits[11 * 8];
__device__ int   g_tpv[11];
__device__ float g_msgbias[3 * 5 * 256];      // folded bond-emb @ Wmsg[256:] + bmsg
__device__ float g_wmsg_tf[3 * 256 * 256];    // pre-rounded tf32 weights
__device__ float g_wself_tf[3 * 256 * 256];
__device__ float g_bcwcat_tf[256 * 256];      // [W1top | W1bot] concatenated, tf32

__device__ __forceinline__ float f2tff(float x) {
    unsigned r;
    asm("cvt.rna.tf32.f32 %0, %1;" : "=r"(r) : "f"(x));
    return __uint_as_float(r);
}
__device__ __forceinline__ float4 f2tff4(float4 v) {
    v.x = f2tff(v.x); v.y = f2tff(v.y); v.z = f2tff(v.z); v.w = f2tff(v.w);
    return v;
}

__device__ __forceinline__ void mma_tf32(float c[4],
    unsigned a0, unsigned a1, unsigned a2, unsigned a3,
    unsigned b0, unsigned b1)
{
    asm volatile(
        "mma.sync.aligned.m16n8k8.row.col.f32.tf32.tf32.f32 "
        "{%0,%1,%2,%3}, {%4,%5,%6,%7}, {%8,%9}, {%0,%1,%2,%3};"
        : "+f"(c[0]), "+f"(c[1]), "+f"(c[2]), "+f"(c[3])
        : "r"(a0), "r"(a1), "r"(a2), "r"(a3), "r"(b0), "r"(b1));
}

__device__ __forceinline__ void cpasync16(void* sptr, const void* g) {
    uint32_t sa = (uint32_t)__cvta_generic_to_shared(sptr);
    asm volatile("cp.async.cg.shared.global [%0], [%1], 16;" :: "r"(sa), "l"(g) : "memory");
}

// Pipelined 32xK x Kx256 tf32 mainloop. As: [32][36], WsA/WsB: [32][264].
__device__ __forceinline__ void gemm_mainloop(
    float c[2][4][4], const float* __restrict__ hin, const float* __restrict__ wtf,
    int nb, int ksteps, float (*As)[36], float (*WsA)[264], float (*WsB)[264])
{
    int tid = threadIdx.x;
    int warp = tid >> 5, lane = tid & 31;
    int n0 = warp * 32;
    const int lr = lane >> 2, lc = lane & 3;
    const int arow = tid >> 3, ac4 = (tid & 7) * 4;

    // prologue: W tile 0 async into WsA; A tile 0 into registers
    float4 aNext = *(const float4*)&hin[(size_t)(nb + arow) * HID + ac4];
#pragma unroll
    for (int i = 0; i < 8; i++) {
        int idx = tid + 256 * i;
        int k = idx >> 6, c4 = (idx & 63) * 4;
        cpasync16(&WsA[k][c4], &wtf[(size_t)k * HID + c4]);
    }
    asm volatile("cp.async.commit_group;" ::: "memory");

    for (int kt = 0; kt < ksteps; kt++) {
        float (*Wcur)[264] = (kt & 1) ? WsB : WsA;
        float (*Wnxt)[264] = (kt & 1) ? WsA : WsB;
        float4 aCur = aNext;
        __syncthreads();                       // prev compute done: safe to touch As/Wnxt
        bool next = (kt + 1 < ksteps);
        if (next) {
            int k0n = (kt + 1) * 32;
#pragma unroll
            for (int i = 0; i < 8; i++) {
                int idx = tid + 256 * i;
                int k = idx >> 6, c4 = (idx & 63) * 4;
                cpasync16(&Wnxt[k][c4], &wtf[(size_t)(k0n + k) * HID + c4]);
            }
            asm volatile("cp.async.commit_group;" ::: "memory");
            aNext = *(const float4*)&hin[(size_t)(nb + arow) * HID + k0n + ac4];
        }
        *(float4*)&As[arow][ac4] = f2tff4(aCur);
        if (next) asm volatile("cp.async.wait_group 1;" ::: "memory");
        else      asm volatile("cp.async.wait_group 0;" ::: "memory");
        __syncthreads();
#pragma unroll
        for (int ks = 0; ks < 4; ks++) {
            int kk = ks * 8;
            unsigned b[4][2];
#pragma unroll
            for (int n = 0; n < 4; n++) {
                int nc = n0 + n * 8 + lr;
                b[n][0] = __float_as_uint(Wcur[kk + lc][nc]);
                b[n][1] = __float_as_uint(Wcur[kk + 4 + lc][nc]);
            }
#pragma unroll
            for (int m = 0; m < 2; m++) {
                int r = m * 16 + lr;
                unsigned a0 = __float_as_uint(As[r][kk + lc]);
                unsigned a1 = __float_as_uint(As[r + 8][kk + lc]);
                unsigned a2 = __float_as_uint(As[r][kk + 4 + lc]);
                unsigned a3 = __float_as_uint(As[r + 8][kk + 4 + lc]);
#pragma unroll
                for (int n = 0; n < 4; n++)
                    mma_tf32(c[m][n], a0, a1, a2, a3, b[n][0], b[n][1]);
            }
        }
    }
}

#define SMEM_PIPE ((32 * 36 + 2 * 32 * 264) * 4)

// ============================================================
// Prep: type-pred MLP, bond-bias fold, tf32 weight pre-round
// (wmsg top / wself / bc_w1 concat), zero counts
// ============================================================
__global__ void k_prep(const float* __restrict__ atom_emb,
                       const float* __restrict__ vp_w1, const float* __restrict__ vp_b1,
                       const float* __restrict__ vp_w2, const float* __restrict__ vp_b2,
                       const float* __restrict__ wmsg, const float* __restrict__ bmsg,
                       const float* __restrict__ bond_emb,
                       const float* __restrict__ wself, const float* __restrict__ bcw1)
{
    int b = blockIdx.x;
    int tid = threadIdx.x;
    if (b == 0) {
        if (tid >= 11) return;
        int t = tid;
        float z[32];
        for (int j = 0; j < 32; j++) {
            float s = vp_b1[j];
            for (int k = 0; k < 64; k++) s += atom_emb[t * 64 + k] * vp_w1[k * 32 + j];
            z[j] = fmaxf(s, 0.f);
        }
        float best = -1e30f; int bi = 0;
        for (int j = 0; j < 8; j++) {
            float s = vp_b2[j];
            for (int k = 0; k < 32; k++) s += z[k] * vp_w2[k * 8 + j];
            g_tlogits[t * 8 + j] = s;
            if (s > best) { best = s; bi = j; }
        }
        g_tpv[t] = bi + 1;
    } else if (b < 16) {
        int idx = b - 1;
        int l = idx / 5, bt = idx % 5;
        const float* w = wmsg + (size_t)l * 320 * HID;
        float s = bmsg[l * HID + tid];
#pragma unroll 8
        for (int j = 0; j < 64; j++)
            s += bond_emb[bt * 64 + j] * w[(size_t)(256 + j) * HID + tid];
        g_msgbias[(size_t)idx * 256 + tid] = s;
    } else if (b < 16 + 768) {
        int i = (b - 16) * 256 + tid;        // over 3*65536
        int l = i >> 16, rest = i & 65535;
        g_wmsg_tf[i] = f2tff(wmsg[(size_t)l * 320 * 256 + rest]);
    } else if (b < 16 + 1536) {
        int i = (b - 784) * 256 + tid;
        g_wself_tf[i] = f2tff(wself[i]);
    } else if (b < 16 + 1792) {
        int i = (b - 1552) * 256 + tid;      // over 256*256
        int k = i >> 8, n = i & 255;
        float v = (n < 128) ? bcw1[(size_t)k * 128 + n]
                            : bcw1[(size_t)(256 + k) * 128 + (n - 128)];
        g_bcwcat_tf[i] = f2tff(v);
    } else {
        int i = (b - 1808) * 256 + tid;
        if (i < NN) g_cnt[i] = 0;
    }
}

// ============================================================
// Node init
// ============================================================
__global__ void k_node_init(const float* __restrict__ x,
                            const float* __restrict__ atom_emb,
                            float* __restrict__ out_vlog)
{
    int gid = blockIdx.x * blockDim.x + threadIdx.x;
    int n = gid >> 5, lane = gid & 31;
    if (n >= NN) return;
    int at = (int)x[(size_t)n * 16];
    at = min(max(at, 0), 10);
    int pv = g_tpv[at];
    if (lane == 0) { g_atype[n] = at; g_pv[n] = pv; }
    if (lane < 8) out_vlog[(size_t)n * 8 + lane] = g_tlogits[at * 8 + lane];
#pragma unroll
    for (int r = 0; r < 8; r++) {
        int c = lane + 32 * r;
        float v;
        if (c < 64)      v = atom_emb[at * 64 + c];
        else if (c < 72) v = (c - 64 == pv - 1) ? 1.f : 0.f;
        else             v = 0.f;
        g_h0[(size_t)n * HID + c] = v;
    }
}

// ============================================================
// CSR build: count -> 3-phase parallel scan (+viol output) -> scatter
// ============================================================
__global__ void k_count(const int* __restrict__ edge_index)
{
    int e = blockIdx.x * blockDim.x + threadIdx.x;
    if (e < NE) atomicAdd(&g_cnt[edge_index[e]], 1);
}

__global__ void k_scan1()
{
    __shared__ int sh[32];
    int t = threadIdx.x;
    int n = blockIdx.x * 1024 + t;
    int c = (n < NN) ? g_cnt[n] : 0;
#pragma unroll
    for (int o = 16; o > 0; o >>= 1) c += __shfl_down_sync(0xffffffffu, c, o);
    if ((t & 31) == 0) sh[t >> 5] = c;
    __syncthreads();
    if (t < 32) {
        int v = sh[t];
#pragma unroll
        for (int o = 16; o > 0; o >>= 1) v += __shfl_down_sync(0xffffffffu, v, o);
        if (t == 0) g_bsum[blockIdx.x] = v;
    }
}

__global__ void k_scan2()
{
    __shared__ int sh[128];
    int t = threadIdx.x;
    int v = (t < 98) ? g_bsum[t] : 0;
    sh[t] = v;
    __syncthreads();
    for (int off = 1; off < 128; off <<= 1) {
        int u = (t >= off) ? sh[t - off] : 0;
        __syncthreads();
        sh[t] += u;
        __syncthreads();
    }
    if (t < 98) g_boff[t] = sh[t] - v;
    if (t == 97) g_rowptr[NN] = sh[97];
}

__global__ void k_scan3(float* __restrict__ out_viol)
{
    __shared__ int sh[1024];
    int t = threadIdx.x;
    int n = blockIdx.x * 1024 + t;
    int c = (n < NN) ? g_cnt[n] : 0;
    sh[t] = c;
    __syncthreads();
    for (int off = 1; off < 1024; off <<= 1) {
        int u = (t >= off) ? sh[t - off] : 0;
        __syncthreads();
        sh[t] += u;
        __syncthreads();
    }
    if (n < NN) {
        int excl = sh[t] - c + g_boff[blockIdx.x];
        g_rowptr[n] = excl;
        g_cur[n] = excl;
        g_deg[n] = (float)c;
        out_viol[n] = fmaxf((float)c - (float)g_pv[n], 0.f);
    }
}

__global__ void k_scatter(const int* __restrict__ edge_index,
                          const float* __restrict__ edge_attr)
{
    int e = blockIdx.x * blockDim.x + threadIdx.x;
    if (e < NE) {
        int pos = atomicAdd(&g_cur[edge_index[e]], 1);
        g_ecol[pos] = edge_index[NE + e];
        g_ebt[pos] = min(max((int)edge_attr[(size_t)e * 4], 0), 4);
    }
}

// ============================================================
// Generic node GEMM (pipelined): out = hin @ wtf, [32 x 256]
// ============================================================
__global__ __launch_bounds__(256, 3) void k_gemm(const float* __restrict__ hin,
        const float* __restrict__ wtf, float* __restrict__ outp, int ksteps)
{
    extern __shared__ float sm[];
    float (*As)[36] = (float(*)[36])sm;
    float (*WsA)[264] = (float(*)[264])(sm + 32 * 36);
    float (*WsB)[264] = (float(*)[264])(sm + 32 * 36 + 32 * 264);
    int tid = threadIdx.x;
    int nb = blockIdx.x * 32;
    int warp = tid >> 5, lane = tid & 31;
    int n0 = warp * 32;
    float c[2][4][4];
#pragma unroll
    for (int m = 0; m < 2; m++)
#pragma unroll
        for (int n = 0; n < 4; n++)
#pragma unroll
            for (int j = 0; j < 4; j++) c[m][n][j] = 0.f;

    gemm_mainloop(c, hin, wtf, nb, ksteps, As, WsA, WsB);

    int g = lane >> 2, cc = 2 * (lane & 3);
#pragma unroll
    for (int m = 0; m < 2; m++) {
        int row0 = nb + m * 16 + g;
        int row1 = row0 + 8;
#pragma unroll
        for (int n = 0; n < 4; n++) {
            int col = n0 + n * 8 + cc;
            *(float2*)&outp[(size_t)row0 * HID + col] = make_float2(c[m][n][0], c[m][n][1]);
            *(float2*)&outp[(size_t)row1 * HID + col] = make_float2(c[m][n][2], c[m][n][3]);
        }
    }
}

// ============================================================
// self GEMM + aggregation (pipelined):
// h_new = relu(h @ Wself + b + sum_in relu(t[col] + msgbias[bt]))
// Last layer fuses valence damping, writes out_h.
// ============================================================
__global__ __launch_bounds__(256, 3) void k_selfagg(int ping, int ksteps, int l,
        const float* __restrict__ bself, int damp, float* __restrict__ out_h)
{
    extern __shared__ float sm[];
    float (*As)[36] = (float(*)[36])sm;
    float (*WsA)[264] = (float(*)[264])(sm + 32 * 36);
    float (*WsB)[264] = (float(*)[264])(sm + 32 * 36 + 32 * 264);
    const float* __restrict__ hin  = ping ? g_h1 : g_h0;
    float* __restrict__ hout       = damp ? out_h : (ping ? g_h0 : g_h1);
    const float* __restrict__ wtf = g_wself_tf + (size_t)l * 65536;
    int tid = threadIdx.x;
    int nb = blockIdx.x * 32;
    int warp = tid >> 5, lane = tid & 31;
    int n0 = warp * 32;
    float c[2][4][4];
#pragma unroll
    for (int m = 0; m < 2; m++)
#pragma unroll
        for (int n = 0; n < 4; n++)
#pragma unroll
            for (int j = 0; j < 4; j++) c[m][n][j] = 0.f;

    gemm_mainloop(c, hin, wtf, nb, ksteps, As, WsA, WsB);

    // stage msgbias[l] (5x256) into shared (reuse WsA region)
    __syncthreads();
    float* smb = sm + 32 * 36;
    {
        const float* mb = g_msgbias + (size_t)l * 1280;
#pragma unroll
        for (int i = 0; i < 5; i++) smb[tid + 256 * i] = mb[tid + 256 * i];
    }
    __syncthreads();

    int g = lane >> 2, cc = 2 * (lane & 3);
#pragma unroll
    for (int m = 0; m < 2; m++) {
        int row0 = nb + m * 16 + g;
        int row1 = row0 + 8;
        int s0 = __ldg(&g_rowptr[row0]), e0 = __ldg(&g_rowptr[row0 + 1]);
        for (int j = s0; j < e0; j++) {
            const float* tr = &g_t[(size_t)__ldg(&g_ecol[j]) * HID];
            const float* mb = smb + __ldg(&g_ebt[j]) * 256;
#pragma unroll
            for (int n = 0; n < 4; n++) {
                int col = n0 + n * 8 + cc;
                float2 v = *(const float2*)&tr[col];
                c[m][n][0] += fmaxf(v.x + mb[col],     0.f);
                c[m][n][1] += fmaxf(v.y + mb[col + 1], 0.f);
            }
        }
        int s1 = __ldg(&g_rowptr[row1]), e1 = __ldg(&g_rowptr[row1 + 1]);
        for (int j = s1; j < e1; j++) {
            const float* tr = &g_t[(size_t)__ldg(&g_ecol[j]) * HID];
            const float* mb = smb + __ldg(&g_ebt[j]) * 256;
#pragma unroll
            for (int n = 0; n < 4; n++) {
                int col = n0 + n * 8 + cc;
                float2 v = *(const float2*)&tr[col];
                c[m][n][2] += fmaxf(v.x + mb[col],     0.f);
                c[m][n][3] += fmaxf(v.y + mb[col + 1], 0.f);
            }
        }
        float sc0 = 1.f, sc1 = 1.f;
        if (damp) {
            sc0 = 1.f / (1.f + fmaxf((float)(e0 - s0) - (float)g_pv[row0], 0.f));
            sc1 = 1.f / (1.f + fmaxf((float)(e1 - s1) - (float)g_pv[row1], 0.f));
        }
#pragma unroll
        for (int n = 0; n < 4; n++) {
            int col = n0 + n * 8 + cc;
            float b0 = __ldg(&bself[col]), b1 = __ldg(&bself[col + 1]);
            float2 r0, r1;
            r0.x = fmaxf(c[m][n][0] + b0, 0.f) * sc0;
            r0.y = fmaxf(c[m][n][1] + b1, 0.f) * sc0;
            r1.x = fmaxf(c[m][n][2] + b0, 0.f) * sc1;
            r1.y = fmaxf(c[m][n][3] + b1, 0.f) * sc1;
            *(float2*)&hout[(size_t)row0 * HID + col] = r0;
            *(float2*)&hout[(size_t)row1 * HID + col] = r1;
        }
    }
}

// ============================================================
// Bond head: stage1 = gather relu(U[row]+V[col]+pv terms+b1),
// stages 2-3 SIMT. No MMA here.
// ============================================================
__global__ __launch_bounds__(256) void k_bc(
        const float* __restrict__ w1, const float* __restrict__ b1,
        const float* __restrict__ w2, const float* __restrict__ b2,
        const float* __restrict__ w3, const float* __restrict__ b3,
        const int* __restrict__ edge_index, float* __restrict__ out_bl)
{
    __shared__ float T1[32][132];
    __shared__ float T2[32][65];
    __shared__ float Ws[32][68];
    __shared__ float s_wpr[128], s_wpc[128], s_bb[128];
    __shared__ int s_row[32], s_col[32], s_atr[32], s_atc[32];
    __shared__ float s_pvr[32], s_pvc[32];
    int tid = threadIdx.x;
    int eb = blockIdx.x * 32;
    if (tid < 32) {
        int e = eb + tid;
        int r = edge_index[e], c = edge_index[NE + e];
        s_row[tid] = r; s_col[tid] = c;
        s_pvr[tid] = (float)g_pv[r]; s_pvc[tid] = (float)g_pv[c];
        s_atr[tid] = g_atype[r];     s_atc[tid] = g_atype[c];
    }
    if (tid < 128) {
        s_wpr[tid] = w1[512 * 128 + tid];
        s_wpc[tid] = w1[513 * 128 + tid];
        s_bb[tid]  = b1[tid];
    }
    __syncthreads();

    // ---- stage 1: gather [32 x 128] from g_uv ----
    int warp = tid >> 5, lane = tid & 31;
    int o = lane * 4;
#pragma unroll
    for (int it = 0; it < 4; it++) {
        int e = warp * 4 + it;
        float4 u = *(const float4*)&g_uv[(size_t)s_row[e] * 256 + o];
        float4 v = *(const float4*)&g_uv[(size_t)s_col[e] * 256 + 128 + o];
        float pr = s_pvr[e], pc = s_pvc[e];
        float4 t;
        t.x = fmaxf(u.x + v.x + pr * s_wpr[o]     + pc * s_wpc[o]     + s_bb[o],     0.f);
        t.y = fmaxf(u.y + v.y + pr * s_wpr[o + 1] + pc * s_wpc[o + 1] + s_bb[o + 1], 0.f);
        t.z = fmaxf(u.z + v.z + pr * s_wpr[o + 2] + pc * s_wpc[o + 2] + s_bb[o + 2], 0.f);
        t.w = fmaxf(u.w + v.w + pr * s_wpr[o + 3] + pc * s_wpc[o + 3] + s_bb[o + 3], 0.f);
        *(float4*)&T1[e][o] = t;
    }
    __syncthreads();

    // ---- stage 2: [32 x 64], K=128 (SIMT) ----
    float acc2[2][4];
#pragma unroll
    for (int i = 0; i < 2; i++)
#pragma unroll
        for (int j = 0; j < 4; j++) acc2[i][j] = 0.f;
    const int tx2 = tid & 15, ty2 = tid >> 4;
    for (int kt = 0; kt < 4; kt++) {
        int k0 = kt * 32;
#pragma unroll
        for (int i = 0; i < 2; i++) {
            int idx = tid + 256 * i;
            int k = idx >> 4, c4 = (idx & 15) * 4;
            *(float4*)&Ws[k][c4] = *(const float4*)&w2[(size_t)(k0 + k) * 64 + c4];
        }
        __syncthreads();
#pragma unroll
        for (int kk = 0; kk < 32; kk++) {
            float a0 = T1[ty2 * 2][k0 + kk];
            float a1 = T1[ty2 * 2 + 1][k0 + kk];
            float4 w = *(const float4*)&Ws[kk][tx2 * 4];
            acc2[0][0] += a0 * w.x; acc2[0][1] += a0 * w.y;
            acc2[0][2] += a0 * w.z; acc2[0][3] += a0 * w.w;
            acc2[1][0] += a1 * w.x; acc2[1][1] += a1 * w.y;
            acc2[1][2] += a1 * w.z; acc2[1][3] += a1 * w.w;
        }
        __syncthreads();
    }
#pragma unroll
    for (int i = 0; i < 2; i++) {
        int e = ty2 * 2 + i;
#pragma unroll
        for (int j = 0; j < 4; j++) {
            int oo = tx2 * 4 + j;
            T2[e][oo] = fmaxf(acc2[i][j] + __ldg(&b2[oo]), 0.f);
        }
    }
    __syncthreads();

    // ---- stage 3: [32 x 4], K=64, + chemical penalties ----
    if (tid < 128) {
        int e = tid >> 2, oo = tid & 3;
        float s = __ldg(&b3[oo]);
#pragma unroll
        for (int k = 0; k < 64; k++) s += T2[e][k] * __ldg(&w3[k * 4 + oo]);
        int ar = s_atr[e], ac = s_atc[e];
        float pr = s_pvr[e], pc = s_pvc[e];
        bool hal = (ar == 4) || (ar == 5) || (ac == 4) || (ac == 5);
        bool l1 = (pr <= 1.f) || (pc <= 1.f);
        bool l2 = (pr <= 2.f) || (pc <= 2.f);
        float pen = 0.f;
        if (oo >= 1) { if (hal) pen -= 100.f; if (l1) pen -= 50.f; }
        if (oo == 2) { if (l2) pen -= 50.f; }
        out_bl[(size_t)(eb + e) * 4 + oo] = s + pen;
    }
}

// ============================================================
// Chem head (SIMT; small)
// ============================================================
__global__ __launch_bounds__(256) void k_cp(const float* __restrict__ hfin,
        const float* __restrict__ w1, const float* __restrict__ b1,
        const float* __restrict__ w2, const float* __restrict__ b2,
        float* __restrict__ out_cp)
{
    __shared__ float As[32][36];
    __shared__ float Ws[32][132];
    __shared__ float T1[32][129];
    int tid = threadIdx.x;
    int nb = blockIdx.x * 32;
    float acc[4][4];
#pragma unroll
    for (int i = 0; i < 4; i++)
#pragma unroll
        for (int j = 0; j < 4; j++) acc[i][j] = 0.f;
    const int tx = tid & 31, ty = tid >> 5;
    const int arow = tid >> 3, ac4 = (tid & 7) * 4;
    for (int kt = 0; kt < 8; kt++) {
        int k0 = kt * 32;
        *(float4*)&As[arow][ac4] =
            *(const float4*)&hfin[(size_t)(nb + arow) * HID + k0 + ac4];
#pragma unroll
        for (int i = 0; i < 4; i++) {
            int idx = tid + 256 * i;
            int k = idx >> 5, c4 = (idx & 31) * 4;
            *(float4*)&Ws[k][c4] = *(const float4*)&w1[(size_t)(k0 + k) * 128 + c4];
        }
        __syncthreads();
#pragma unroll
        for (int kk = 0; kk < 32; kk++) {
            float a[4];
#pragma unroll
            for (int i = 0; i < 4; i++) a[i] = As[ty * 4 + i][kk];
            float4 w = *(const float4*)&Ws[kk][tx * 4];
#pragma unroll
            for (int i = 0; i < 4; i++) {
                acc[i][0] += a[i] * w.x; acc[i][1] += a[i] * w.y;
                acc[i][2] += a[i] * w.z; acc[i][3] += a[i] * w.w;
            }
        }
        __syncthreads();
    }
#pragma unroll
    for (int i = 0; i < 4; i++) {
        int e = ty * 4 + i;
#pragma unroll
        for (int j = 0; j < 4; j++) {
            int o = tx * 4 + j;
            T1[e][o] = fmaxf(acc[i][j] + __ldg(&b1[o]), 0.f);
        }
    }
    __syncthreads();

    float acc2[4] = {0.f, 0.f, 0.f, 0.f};
    const int tx2 = tid & 7, ty2 = tid >> 3;
    for (int kt = 0; kt < 4; kt++) {
        int k0 = kt * 32;
        {
            int k = tid >> 3, c4 = (tid & 7) * 4;
            *(float4*)&Ws[k][c4] = *(const float4*)&w2[(size_t)(k0 + k) * 32 + c4];
        }
        __syncthreads();
#pragma unroll
        for (int kk = 0; kk < 32; kk++) {
            float a = T1[ty2][k0 + kk];
            float4 w = *(const float4*)&Ws[kk][tx2 * 4];
            acc2[0] += a * w.x; acc2[1] += a * w.y;
            acc2[2] += a * w.z; acc2[3] += a * w.w;
        }
        __syncthreads();
    }
#pragma unroll
    for (int j = 0; j < 4; j++) {
        int o = tx2 * 4 + j;
        out_cp[(size_t)(nb + ty2) * 32 + o] = acc2[j] + __ldg(&b2[o]);
    }
}

// ============================================================
extern "C" void kernel_launch(void* const* d_in, const int* in_sizes, int n_in,
                              void* d_out, int out_size)
{
    (void)in_sizes; (void)n_in; (void)out_size;
    const float* x         = (const float*)d_in[0];
    const float* edge_attr = (const float*)d_in[1];
    const float* atom_emb  = (const float*)d_in[2];
    const float* bond_emb  = (const float*)d_in[3];
    const float* vp_w1     = (const float*)d_in[4];
    const float* vp_b1     = (const float*)d_in[5];
    const float* vp_w2     = (const float*)d_in[6];
    const float* vp_b2     = (const float*)d_in[7];
    const float* gnn_wself = (const float*)d_in[8];
    const float* gnn_bself = (const float*)d_in[9];
    const float* gnn_wmsg  = (const float*)d_in[10];
    const float* gnn_bmsg  = (const float*)d_in[11];
    const float* bc_w1     = (const float*)d_in[12];
    const float* bc_b1     = (const float*)d_in[13];
    const float* bc_w2     = (const float*)d_in[14];
    const float* bc_b2     = (const float*)d_in[15];
    const float* bc_w3     = (const float*)d_in[16];
    const float* bc_b3     = (const float*)d_in[17];
    const float* cp_w1     = (const float*)d_in[18];
    const float* cp_b1     = (const float*)d_in[19];
    const float* cp_w2     = (const float*)d_in[20];
    const float* cp_b2     = (const float*)d_in[21];
    const int* edge_index  = (const int*)d_in[22];

    float* out      = (float*)d_out;
    float* out_h    = out;                                 // [N,256]
    float* out_cp   = out_h    + (size_t)NN * HID;         // [N,32]
    float* out_vlog = out_cp   + (size_t)NN * 32;          // [N,8]
    float* out_bl   = out_vlog + (size_t)NN * 8;           // [E,4]
    float* out_viol = out_bl   + (size_t)NE * 4;           // [N]

    cudaFuncSetAttribute(k_gemm, cudaFuncAttributeMaxDynamicSharedMemorySize, SMEM_PIPE);
    cudaFuncSetAttribute(k_selfagg, cudaFuncAttributeMaxDynamicSharedMemorySize, SMEM_PIPE);

    // resolve device-global addresses
    float *p_h0, *p_h1, *p_t, *p_uv, *p_wmsg, *p_bccat;
    cudaGetSymbolAddress((void**)&p_h0,    g_h0);
    cudaGetSymbolAddress((void**)&p_h1,    g_h1);
    cudaGetSymbolAddress((void**)&p_t,     g_t);
    cudaGetSymbolAddress((void**)&p_uv,    g_uv);
    cudaGetSymbolAddress((void**)&p_wmsg,  g_wmsg_tf);
    cudaGetSymbolAddress((void**)&p_bccat, g_bcwcat_tf);

    k_prep<<<2199, 256>>>(atom_emb, vp_w1, vp_b1, vp_w2, vp_b2,
                          gnn_wmsg, gnn_bmsg, bond_emb, gnn_wself, bc_w1);
    k_node_init<<<(NN * 32 + 255) / 256, 256>>>(x, atom_emb, out_vlog);
    k_count<<<(NE + 255) / 256, 256>>>(edge_index);
    k_gemm<<<NN / 32, 256, SMEM_PIPE>>>(p_h0, p_wmsg, p_t, 3);   // layer-0 t (captured)
    k_scan1<<<98, 1024>>>();
    k_scan2<<<1, 128>>>();
    k_scan3<<<98, 1024>>>(out_viol);
    k_scatter<<<(NE + 255) / 256, 256>>>(edge_index, edge_attr);

    // layer 0: self+agg (h0 -> h1)
    k_selfagg<<<NN / 32, 256, SMEM_PIPE>>>(0, 3, 0, gnn_bself + 0 * HID, 0, out_h);
    // layer 1: (h1 -> h0)
    k_gemm<<<NN / 32, 256, SMEM_PIPE>>>(p_h1, p_wmsg + 65536, p_t, 8);
    k_selfagg<<<NN / 32, 256, SMEM_PIPE>>>(1, 8, 1, gnn_bself + 1 * HID, 0, out_h);
    // layer 2: (h0 -> out_h, damped)
    k_gemm<<<NN / 32, 256, SMEM_PIPE>>>(p_h0, p_wmsg + 2 * 65536, p_t, 8);
    k_selfagg<<<NN / 32, 256, SMEM_PIPE>>>(0, 8, 2, gnn_bself + 2 * HID, 1, out_h);

    // bond head precompute: UV = out_h @ [W1top|W1bot]
    k_gemm<<<NN / 32, 256, SMEM_PIPE>>>(out_h, p_bccat, p_uv, 8);

    k_bc<<<NE / 32, 256>>>(bc_w1, bc_b1, bc_w2, bc_b2, bc_w3, bc_b3,
                           edge_index, out_bl);
    k_cp<<<NN / 32, 256>>>(out_h, cp_w1, cp_b1, cp_w2, cp_b2, out_cp);
}

// round 13
// speedup vs baseline: 1.5827x; 1.0784x over previous
#include <cuda_runtime.h>
#include <cstdint>

#define NN 100000
#define NE 300000
#define HID 256

// ---- scratch (static device globals; allocation-free) ----
__device__ float g_h0[NN * HID];
__device__ float g_h1[NN * HID];
__device__ float g_t[NN * HID];               // t = h @ Wmsg_top (per node)
__device__ float g_z[NN * HID];               // z = h @ Wself (per node)
__device__ float g_uv[NN * HID];              // [U | V] = h_final @ [W1top|W1bot]
__device__ int   g_atype[NN];
__device__ int   g_pv[NN];
__device__ float g_deg[NN];
__device__ int   g_cnt[NN];
__device__ int   g_rowptr[NN + 1];
__device__ int   g_cur[NN];
__device__ int   g_ecol[NE];                  // CSR-slot -> source node
__device__ int   g_ebt[NE];                   // CSR-slot -> bond type
__device__ int   g_bsum[98];
__device__ int   g_boff[98];
__device__ float g_tlogits[11 * 8];
__device__ int   g_tpv[11];
__device__ float g_msgbias[3 * 5 * 256];      // folded bond-emb @ Wmsg[256:] + bmsg
__device__ float g_wmsg_tf[3 * 256 * 256];    // pre-rounded tf32 weights
__device__ float g_wself_tf[3 * 256 * 256];
__device__ float g_bcwcat_tf[256 * 256];      // [W1top | W1bot] concatenated, tf32

__device__ __forceinline__ float f2tff(float x) {
    unsigned r;
    asm("cvt.rna.tf32.f32 %0, %1;" : "=r"(r) : "f"(x));
    return __uint_as_float(r);
}
__device__ __forceinline__ float4 f2tff4(float4 v) {
    v.x = f2tff(v.x); v.y = f2tff(v.y); v.z = f2tff(v.z); v.w = f2tff(v.w);
    return v;
}

__device__ __forceinline__ void mma_tf32(float c[4],
    unsigned a0, unsigned a1, unsigned a2, unsigned a3,
    unsigned b0, unsigned b1)
{
    asm volatile(
        "mma.sync.aligned.m16n8k8.row.col.f32.tf32.tf32.f32 "
        "{%0,%1,%2,%3}, {%4,%5,%6,%7}, {%8,%9}, {%0,%1,%2,%3};"
        : "+f"(c[0]), "+f"(c[1]), "+f"(c[2]), "+f"(c[3])
        : "r"(a0), "r"(a1), "r"(a2), "r"(a3), "r"(b0), "r"(b1));
}

__device__ __forceinline__ void cpasync16(void* sptr, const void* g) {
    uint32_t sa = (uint32_t)__cvta_generic_to_shared(sptr);
    asm volatile("cp.async.cg.shared.global [%0], [%1], 16;" :: "r"(sa), "l"(g) : "memory");
}

// Pipelined 32xK x Kx256 tf32 mainloop. As: [32][36], WsA/WsB: [32][264].
// cvt=0 when hin is already tf32-pre-rounded.
__device__ __forceinline__ void gemm_mainloop(
    float c[2][4][4], const float* __restrict__ hin, const float* __restrict__ wtf,
    int nb, int ksteps, int cvt, float (*As)[36], float (*WsA)[264], float (*WsB)[264])
{
    int tid = threadIdx.x;
    int warp = tid >> 5, lane = tid & 31;
    int n0 = warp * 32;
    const int lr = lane >> 2, lc = lane & 3;
    const int arow = tid >> 3, ac4 = (tid & 7) * 4;

    // prologue: W tile 0 async into WsA; A tile 0 into registers
    float4 aNext = *(const float4*)&hin[(size_t)(nb + arow) * HID + ac4];
#pragma unroll
    for (int i = 0; i < 8; i++) {
        int idx = tid + 256 * i;
        int k = idx >> 6, c4 = (idx & 63) * 4;
        cpasync16(&WsA[k][c4], &wtf[(size_t)k * HID + c4]);
    }
    asm volatile("cp.async.commit_group;" ::: "memory");

    for (int kt = 0; kt < ksteps; kt++) {
        float (*Wcur)[264] = (kt & 1) ? WsB : WsA;
        float (*Wnxt)[264] = (kt & 1) ? WsA : WsB;
        float4 aCur = aNext;
        __syncthreads();                       // prev compute done: safe to touch As/Wnxt
        bool next = (kt + 1 < ksteps);
        if (next) {
            int k0n = (kt + 1) * 32;
#pragma unroll
            for (int i = 0; i < 8; i++) {
                int idx = tid + 256 * i;
                int k = idx >> 6, c4 = (idx & 63) * 4;
                cpasync16(&Wnxt[k][c4], &wtf[(size_t)(k0n + k) * HID + c4]);
            }
            asm volatile("cp.async.commit_group;" ::: "memory");
            aNext = *(const float4*)&hin[(size_t)(nb + arow) * HID + k0n + ac4];
        }
        *(float4*)&As[arow][ac4] = cvt ? f2tff4(aCur) : aCur;
        if (next) asm volatile("cp.async.wait_group 1;" ::: "memory");
        else      asm volatile("cp.async.wait_group 0;" ::: "memory");
        __syncthreads();
#pragma unroll
        for (int ks = 0; ks < 4; ks++) {
            int kk = ks * 8;
            unsigned b[4][2];
#pragma unroll
            for (int n = 0; n < 4; n++) {
                int nc = n0 + n * 8 + lr;
                b[n][0] = __float_as_uint(Wcur[kk + lc][nc]);
                b[n][1] = __float_as_uint(Wcur[kk + 4 + lc][nc]);
            }
#pragma unroll
            for (int m = 0; m < 2; m++) {
                int r = m * 16 + lr;
                unsigned a0 = __float_as_uint(As[r][kk + lc]);
                unsigned a1 = __float_as_uint(As[r + 8][kk + lc]);
                unsigned a2 = __float_as_uint(As[r][kk + 4 + lc]);
                unsigned a3 = __float_as_uint(As[r + 8][kk + 4 + lc]);
#pragma unroll
                for (int n = 0; n < 4; n++)
                    mma_tf32(c[m][n], a0, a1, a2, a3, b[n][0], b[n][1]);
            }
        }
    }
}

#define SMEM_PIPE ((32 * 36 + 2 * 32 * 264) * 4)

// ============================================================
// Prep: type-pred MLP, bond-bias fold, tf32 weight pre-round
// ============================================================
__global__ void k_prep(const float* __restrict__ atom_emb,
                       const float* __restrict__ vp_w1, const float* __restrict__ vp_b1,
                       const float* __restrict__ vp_w2, const float* __restrict__ vp_b2,
                       const float* __restrict__ wmsg, const float* __restrict__ bmsg,
                       const float* __restrict__ bond_emb,
                       const float* __restrict__ wself, const float* __restrict__ bcw1)
{
    int b = blockIdx.x;
    int tid = threadIdx.x;
    if (b == 0) {
        if (tid >= 11) return;
        int t = tid;
        float z[32];
        for (int j = 0; j < 32; j++) {
            float s = vp_b1[j];
            for (int k = 0; k < 64; k++) s += atom_emb[t * 64 + k] * vp_w1[k * 32 + j];
            z[j] = fmaxf(s, 0.f);
        }
        float best = -1e30f; int bi = 0;
        for (int j = 0; j < 8; j++) {
            float s = vp_b2[j];
            for (int k = 0; k < 32; k++) s += z[k] * vp_w2[k * 8 + j];
            g_tlogits[t * 8 + j] = s;
            if (s > best) { best = s; bi = j; }
        }
        g_tpv[t] = bi + 1;
    } else if (b < 16) {
        int idx = b - 1;
        int l = idx / 5, bt = idx % 5;
        const float* w = wmsg + (size_t)l * 320 * HID;
        float s = bmsg[l * HID + tid];
#pragma unroll 8
        for (int j = 0; j < 64; j++)
            s += bond_emb[bt * 64 + j] * w[(size_t)(256 + j) * HID + tid];
        g_msgbias[(size_t)idx * 256 + tid] = s;
    } else if (b < 16 + 768) {
        int i = (b - 16) * 256 + tid;        // over 3*65536
        int l = i >> 16, rest = i & 65535;
        g_wmsg_tf[i] = f2tff(wmsg[(size_t)l * 320 * 256 + rest]);
    } else if (b < 16 + 1536) {
        int i = (b - 784) * 256 + tid;
        g_wself_tf[i] = f2tff(wself[i]);
    } else if (b < 16 + 1792) {
        int i = (b - 1552) * 256 + tid;      // over 256*256
        int k = i >> 8, n = i & 255;
        float v = (n < 128) ? bcw1[(size_t)k * 128 + n]
                            : bcw1[(size_t)(256 + k) * 128 + (n - 128)];
        g_bcwcat_tf[i] = f2tff(v);
    } else {
        int i = (b - 1808) * 256 + tid;
        if (i < NN) g_cnt[i] = 0;
    }
}

// ============================================================
// Node init: h0 stored PRE-ROUNDED to tf32 (only GEMMs consume it)
// ============================================================
__global__ void k_node_init(const float* __restrict__ x,
                            const float* __restrict__ atom_emb,
                            float* __restrict__ out_vlog)
{
    int gid = blockIdx.x * blockDim.x + threadIdx.x;
    int n = gid >> 5, lane = gid & 31;
    if (n >= NN) return;
    int at = (int)x[(size_t)n * 16];
    at = min(max(at, 0), 10);
    int pv = g_tpv[at];
    if (lane == 0) { g_atype[n] = at; g_pv[n] = pv; }
    if (lane < 8) out_vlog[(size_t)n * 8 + lane] = g_tlogits[at * 8 + lane];
#pragma unroll
    for (int r = 0; r < 8; r++) {
        int c = lane + 32 * r;
        float v;
        if (c < 64)      v = f2tff(atom_emb[at * 64 + c]);
        else if (c < 72) v = (c - 64 == pv - 1) ? 1.f : 0.f;
        else             v = 0.f;
        g_h0[(size_t)n * HID + c] = v;
    }
}

// ============================================================
// CSR build: count -> 3-phase parallel scan (+viol output) -> scatter
// ============================================================
__global__ void k_count(const int* __restrict__ edge_index)
{
    int e = blockIdx.x * blockDim.x + threadIdx.x;
    if (e < NE) atomicAdd(&g_cnt[edge_index[e]], 1);
}

__global__ void k_scan1()
{
    __shared__ int sh[32];
    int t = threadIdx.x;
    int n = blockIdx.x * 1024 + t;
    int c = (n < NN) ? g_cnt[n] : 0;
#pragma unroll
    for (int o = 16; o > 0; o >>= 1) c += __shfl_down_sync(0xffffffffu, c, o);
    if ((t & 31) == 0) sh[t >> 5] = c;
    __syncthreads();
    if (t < 32) {
        int v = sh[t];
#pragma unroll
        for (int o = 16; o > 0; o >>= 1) v += __shfl_down_sync(0xffffffffu, v, o);
        if (t == 0) g_bsum[blockIdx.x] = v;
    }
}

__global__ void k_scan2()
{
    __shared__ int sh[128];
    int t = threadIdx.x;
    int v = (t < 98) ? g_bsum[t] : 0;
    sh[t] = v;
    __syncthreads();
    for (int off = 1; off < 128; off <<= 1) {
        int u = (t >= off) ? sh[t - off] : 0;
        __syncthreads();
        sh[t] += u;
        __syncthreads();
    }
    if (t < 98) g_boff[t] = sh[t] - v;
    if (t == 97) g_rowptr[NN] = sh[97];
}

__global__ void k_scan3(float* __restrict__ out_viol)
{
    __shared__ int sh[1024];
    int t = threadIdx.x;
    int n = blockIdx.x * 1024 + t;
    int c = (n < NN) ? g_cnt[n] : 0;
    sh[t] = c;
    __syncthreads();
    for (int off = 1; off < 1024; off <<= 1) {
        int u = (t >= off) ? sh[t - off] : 0;
        __syncthreads();
        sh[t] += u;
        __syncthreads();
    }
    if (n < NN) {
        int excl = sh[t] - c + g_boff[blockIdx.x];
        g_rowptr[n] = excl;
        g_cur[n] = excl;
        g_deg[n] = (float)c;
        out_viol[n] = fmaxf((float)c - (float)g_pv[n], 0.f);
    }
}

__global__ void k_scatter(const int* __restrict__ edge_index,
                          const float* __restrict__ edge_attr)
{
    int e = blockIdx.x * blockDim.x + threadIdx.x;
    if (e < NE) {
        int pos = atomicAdd(&g_cur[edge_index[e]], 1);
        g_ecol[pos] = edge_index[NE + e];
        g_ebt[pos] = min(max((int)edge_attr[(size_t)e * 4], 0), 4);
    }
}

// ============================================================
// Generic node GEMM (pipelined): out = hin @ wtf, [32 x 256]
// ============================================================
__global__ __launch_bounds__(256, 3) void k_gemm(const float* __restrict__ hin,
        const float* __restrict__ wtf, float* __restrict__ outp, int ksteps, int cvt)
{
    extern __shared__ float sm[];
    float (*As)[36] = (float(*)[36])sm;
    float (*WsA)[264] = (float(*)[264])(sm + 32 * 36);
    float (*WsB)[264] = (float(*)[264])(sm + 32 * 36 + 32 * 264);
    int tid = threadIdx.x;
    int nb = blockIdx.x * 32;
    int warp = tid >> 5, lane = tid & 31;
    int n0 = warp * 32;
    float c[2][4][4];
#pragma unroll
    for (int m = 0; m < 2; m++)
#pragma unroll
        for (int n = 0; n < 4; n++)
#pragma unroll
            for (int j = 0; j < 4; j++) c[m][n][j] = 0.f;

    gemm_mainloop(c, hin, wtf, nb, ksteps, cvt, As, WsA, WsB);

    int g = lane >> 2, cc = 2 * (lane & 3);
#pragma unroll
    for (int m = 0; m < 2; m++) {
        int row0 = nb + m * 16 + g;
        int row1 = row0 + 8;
#pragma unroll
        for (int n = 0; n < 4; n++) {
            int col = n0 + n * 8 + cc;
            *(float2*)&outp[(size_t)row0 * HID + col] = make_float2(c[m][n][0], c[m][n][1]);
            *(float2*)&outp[(size_t)row1 * HID + col] = make_float2(c[m][n][2], c[m][n][3]);
        }
    }
}

// ============================================================
// Aggregation (lightweight, high-occupancy): one WARP per node.
// h' = relu(z + b + sum_in relu(t[col] + msgbias[bt]))  (+damp / +round)
// Thread owns 8 contiguous cols; warp covers the full 256-col row.
// ============================================================
__global__ __launch_bounds__(256, 5) void k_agg(
        const float* __restrict__ zb, const float* __restrict__ tb,
        const float* __restrict__ bself, int l, int damp, int rnd,
        float* __restrict__ hout)
{
    __shared__ float smb[5 * 256];
    __shared__ float sb[256];
    int tid = threadIdx.x;
    {
        const float* mb = g_msgbias + (size_t)l * 1280;
#pragma unroll
        for (int i = 0; i < 5; i++) smb[tid + 256 * i] = mb[tid + 256 * i];
        sb[tid] = bself[tid];
    }
    __syncthreads();

    int node = blockIdx.x * 8 + (tid >> 5);
    int seg = (tid & 31) * 8;
    int s = __ldg(&g_rowptr[node]);
    int e = __ldg(&g_rowptr[node + 1]);

    float4 a0 = make_float4(0.f, 0.f, 0.f, 0.f);
    float4 a1 = make_float4(0.f, 0.f, 0.f, 0.f);

    int j = s;
    for (; j + 1 < e; j += 2) {            // unroll-2 for MLP
        int c0 = __ldg(&g_ecol[j]),     bt0 = __ldg(&g_ebt[j]);
        int c1 = __ldg(&g_ecol[j + 1]), bt1 = __ldg(&g_ebt[j + 1]);
        const float* r0 = tb + (size_t)c0 * HID + seg;
        const float* r1 = tb + (size_t)c1 * HID + seg;
        float4 x0 = *(const float4*)r0;
        float4 x1 = *(const float4*)(r0 + 4);
        float4 y0 = *(const float4*)r1;
        float4 y1 = *(const float4*)(r1 + 4);
        const float* m0 = smb + bt0 * 256 + seg;
        const float* m1 = smb + bt1 * 256 + seg;
        a0.x += fmaxf(x0.x + m0[0], 0.f); a0.y += fmaxf(x0.y + m0[1], 0.f);
        a0.z += fmaxf(x0.z + m0[2], 0.f); a0.w += fmaxf(x0.w + m0[3], 0.f);
        a1.x += fmaxf(x1.x + m0[4], 0.f); a1.y += fmaxf(x1.y + m0[5], 0.f);
        a1.z += fmaxf(x1.z + m0[6], 0.f); a1.w += fmaxf(x1.w + m0[7], 0.f);
        a0.x += fmaxf(y0.x + m1[0], 0.f); a0.y += fmaxf(y0.y + m1[1], 0.f);
        a0.z += fmaxf(y0.z + m1[2], 0.f); a0.w += fmaxf(y0.w + m1[3], 0.f);
        a1.x += fmaxf(y1.x + m1[4], 0.f); a1.y += fmaxf(y1.y + m1[5], 0.f);
        a1.z += fmaxf(y1.z + m1[6], 0.f); a1.w += fmaxf(y1.w + m1[7], 0.f);
    }
    if (j < e) {
        int c0 = __ldg(&g_ecol[j]), bt0 = __ldg(&g_ebt[j]);
        const float* r0 = tb + (size_t)c0 * HID + seg;
        float4 x0 = *(const float4*)r0;
        float4 x1 = *(const float4*)(r0 + 4);
        const float* m0 = smb + bt0 * 256 + seg;
        a0.x += fmaxf(x0.x + m0[0], 0.f); a0.y += fmaxf(x0.y + m0[1], 0.f);
        a0.z += fmaxf(x0.z + m0[2], 0.f); a0.w += fmaxf(x0.w + m0[3], 0.f);
        a1.x += fmaxf(x1.x + m0[4], 0.f); a1.y += fmaxf(x1.y + m0[5], 0.f);
        a1.z += fmaxf(x1.z + m0[6], 0.f); a1.w += fmaxf(x1.w + m0[7], 0.f);
    }

    const float* zr = zb + (size_t)node * HID + seg;
    float4 z0 = *(const float4*)zr;
    float4 z1 = *(const float4*)(zr + 4);
    float sc = 1.f;
    if (damp)
        sc = 1.f / (1.f + fmaxf((float)(e - s) - (float)__ldg(&g_pv[node]), 0.f));
    float4 o0, o1;
    o0.x = fmaxf(z0.x + sb[seg + 0] + a0.x, 0.f) * sc;
    o0.y = fmaxf(z0.y + sb[seg + 1] + a0.y, 0.f) * sc;
    o0.z = fmaxf(z0.z + sb[seg + 2] + a0.z, 0.f) * sc;
    o0.w = fmaxf(z0.w + sb[seg + 3] + a0.w, 0.f) * sc;
    o1.x = fmaxf(z1.x + sb[seg + 4] + a1.x, 0.f) * sc;
    o1.y = fmaxf(z1.y + sb[seg + 5] + a1.y, 0.f) * sc;
    o1.z = fmaxf(z1.z + sb[seg + 6] + a1.z, 0.f) * sc;
    o1.w = fmaxf(z1.w + sb[seg + 7] + a1.w, 0.f) * sc;
    if (rnd) { o0 = f2tff4(o0); o1 = f2tff4(o1); }   // internal h: pre-round for GEMMs
    float* op = hout + (size_t)node * HID + seg;
    *(float4*)op = o0;
    *(float4*)(op + 4) = o1;
}

// ============================================================
// Bond head: stage1 = gather relu(U[row]+V[col]+pv terms+b1),
// stages 2-3 SIMT. No MMA here.
// ============================================================
__global__ __launch_bounds__(256) void k_bc(
        const float* __restrict__ w1, const float* __restrict__ b1,
        const float* __restrict__ w2, const float* __restrict__ b2,
        const float* __restrict__ w3, const float* __restrict__ b3,
        const int* __restrict__ edge_index, float* __restrict__ out_bl)
{
    __shared__ float T1[32][132];
    __shared__ float T2[32][65];
    __shared__ float Ws[32][68];
    __shared__ float s_wpr[128], s_wpc[128], s_bb[128];
    __shared__ int s_row[32], s_col[32], s_atr[32], s_atc[32];
    __shared__ float s_pvr[32], s_pvc[32];
    int tid = threadIdx.x;
    int eb = blockIdx.x * 32;
    if (tid < 32) {
        int e = eb + tid;
        int r = edge_index[e], c = edge_index[NE + e];
        s_row[tid] = r; s_col[tid] = c;
        s_pvr[tid] = (float)g_pv[r]; s_pvc[tid] = (float)g_pv[c];
        s_atr[tid] = g_atype[r];     s_atc[tid] = g_atype[c];
    }
    if (tid < 128) {
        s_wpr[tid] = w1[512 * 128 + tid];
        s_wpc[tid] = w1[513 * 128 + tid];
        s_bb[tid]  = b1[tid];
    }
    __syncthreads();

    // ---- stage 1: gather [32 x 128] from g_uv ----
    int warp = tid >> 5, lane = tid & 31;
    int o = lane * 4;
#pragma unroll
    for (int it = 0; it < 4; it++) {
        int e = warp * 4 + it;
        float4 u = *(const float4*)&g_uv[(size_t)s_row[e] * 256 + o];
        float4 v = *(const float4*)&g_uv[(size_t)s_col[e] * 256 + 128 + o];
        float pr = s_pvr[e], pc = s_pvc[e];
        float4 t;
        t.x = fmaxf(u.x + v.x + pr * s_wpr[o]     + pc * s_wpc[o]     + s_bb[o],     0.f);
        t.y = fmaxf(u.y + v.y + pr * s_wpr[o + 1] + pc * s_wpc[o + 1] + s_bb[o + 1], 0.f);
        t.z = fmaxf(u.z + v.z + pr * s_wpr[o + 2] + pc * s_wpc[o + 2] + s_bb[o + 2], 0.f);
        t.w = fmaxf(u.w + v.w + pr * s_wpr[o + 3] + pc * s_wpc[o + 3] + s_bb[o + 3], 0.f);
        *(float4*)&T1[e][o] = t;
    }
    __syncthreads();

    // ---- stage 2: [32 x 64], K=128 (SIMT) ----
    float acc2[2][4];
#pragma unroll
    for (int i = 0; i < 2; i++)
#pragma unroll
        for (int j = 0; j < 4; j++) acc2[i][j] = 0.f;
    const int tx2 = tid & 15, ty2 = tid >> 4;
    for (int kt = 0; kt < 4; kt++) {
        int k0 = kt * 32;
#pragma unroll
        for (int i = 0; i < 2; i++) {
            int idx = tid + 256 * i;
            int k = idx >> 4, c4 = (idx & 15) * 4;
            *(float4*)&Ws[k][c4] = *(const float4*)&w2[(size_t)(k0 + k) * 64 + c4];
        }
        __syncthreads();
#pragma unroll
        for (int kk = 0; kk < 32; kk++) {
            float a0 = T1[ty2 * 2][k0 + kk];
            float a1 = T1[ty2 * 2 + 1][k0 + kk];
            float4 w = *(const float4*)&Ws[kk][tx2 * 4];
            acc2[0][0] += a0 * w.x; acc2[0][1] += a0 * w.y;
            acc2[0][2] += a0 * w.z; acc2[0][3] += a0 * w.w;
            acc2[1][0] += a1 * w.x; acc2[1][1] += a1 * w.y;
            acc2[1][2] += a1 * w.z; acc2[1][3] += a1 * w.w;
        }
        __syncthreads();
    }
#pragma unroll
    for (int i = 0; i < 2; i++) {
        int e = ty2 * 2 + i;
#pragma unroll
        for (int j = 0; j < 4; j++) {
            int oo = tx2 * 4 + j;
            T2[e][oo] = fmaxf(acc2[i][j] + __ldg(&b2[oo]), 0.f);
        }
    }
    __syncthreads();

    // ---- stage 3: [32 x 4], K=64, + chemical penalties ----
    if (tid < 128) {
        int e = tid >> 2, oo = tid & 3;
        float s = __ldg(&b3[oo]);
#pragma unroll
        for (int k = 0; k < 64; k++) s += T2[e][k] * __ldg(&w3[k * 4 + oo]);
        int ar = s_atr[e], ac = s_atc[e];
        float pr = s_pvr[e], pc = s_pvc[e];
        bool hal = (ar == 4) || (ar == 5) || (ac == 4) || (ac == 5);
        bool l1 = (pr <= 1.f) || (pc <= 1.f);
        bool l2 = (pr <= 2.f) || (pc <= 2.f);
        float pen = 0.f;
        if (oo >= 1) { if (hal) pen -= 100.f; if (l1) pen -= 50.f; }
        if (oo == 2) { if (l2) pen -= 50.f; }
        out_bl[(size_t)(eb + e) * 4 + oo] = s + pen;
    }
}

// ============================================================
// Chem head (SIMT; small)
// ============================================================
__global__ __launch_bounds__(256) void k_cp(const float* __restrict__ hfin,
        const float* __restrict__ w1, const float* __restrict__ b1,
        const float* __restrict__ w2, const float* __restrict__ b2,
        float* __restrict__ out_cp)
{
    __shared__ float As[32][36];
    __shared__ float Ws[32][132];
    __shared__ float T1[32][129];
    int tid = threadIdx.x;
    int nb = blockIdx.x * 32;
    float acc[4][4];
#pragma unroll
    for (int i = 0; i < 4; i++)
#pragma unroll
        for (int j = 0; j < 4; j++) acc[i][j] = 0.f;
    const int tx = tid & 31, ty = tid >> 5;
    const int arow = tid >> 3, ac4 = (tid & 7) * 4;
    for (int kt = 0; kt < 8; kt++) {
        int k0 = kt * 32;
        *(float4*)&As[arow][ac4] =
            *(const float4*)&hfin[(size_t)(nb + arow) * HID + k0 + ac4];
#pragma unroll
        for (int i = 0; i < 4; i++) {
            int idx = tid + 256 * i;
            int k = idx >> 5, c4 = (idx & 31) * 4;
            *(float4*)&Ws[k][c4] = *(const float4*)&w1[(size_t)(k0 + k) * 128 + c4];
        }
        __syncthreads();
#pragma unroll
        for (int kk = 0; kk < 32; kk++) {
            float a[4];
#pragma unroll
            for (int i = 0; i < 4; i++) a[i] = As[ty * 4 + i][kk];
            float4 w = *(const float4*)&Ws[kk][tx * 4];
#pragma unroll
            for (int i = 0; i < 4; i++) {
                acc[i][0] += a[i] * w.x; acc[i][1] += a[i] * w.y;
                acc[i][2] += a[i] * w.z; acc[i][3] += a[i] * w.w;
            }
        }
        __syncthreads();
    }
#pragma unroll
    for (int i = 0; i < 4; i++) {
        int e = ty * 4 + i;
#pragma unroll
        for (int j = 0; j < 4; j++) {
            int o = tx * 4 + j;
            T1[e][o] = fmaxf(acc[i][j] + __ldg(&b1[o]), 0.f);
        }
    }
    __syncthreads();

    float acc2[4] = {0.f, 0.f, 0.f, 0.f};
    const int tx2 = tid & 7, ty2 = tid >> 3;
    for (int kt = 0; kt < 4; kt++) {
        int k0 = kt * 32;
        {
            int k = tid >> 3, c4 = (tid & 7) * 4;
            *(float4*)&Ws[k][c4] = *(const float4*)&w2[(size_t)(k0 + k) * 32 + c4];
        }
        __syncthreads();
#pragma unroll
        for (int kk = 0; kk < 32; kk++) {
            float a = T1[ty2][k0 + kk];
            float4 w = *(const float4*)&Ws[kk][tx2 * 4];
            acc2[0] += a * w.x; acc2[1] += a * w.y;
            acc2[2] += a * w.z; acc2[3] += a * w.w;
        }
        __syncthreads();
    }
#pragma unroll
    for (int j = 0; j < 4; j++) {
        int o = tx2 * 4 + j;
        out_cp[(size_t)(nb + ty2) * 32 + o] = acc2[j] + __ldg(&b2[o]);
    }
}

// ============================================================
extern "C" void kernel_launch(void* const* d_in, const int* in_sizes, int n_in,
                              void* d_out, int out_size)
{
    (void)in_sizes; (void)n_in; (void)out_size;
    const float* x         = (const float*)d_in[0];
    const float* edge_attr = (const float*)d_in[1];
    const float* atom_emb  = (const float*)d_in[2];
    const float* bond_emb  = (const float*)d_in[3];
    const float* vp_w1     = (const float*)d_in[4];
    const float* vp_b1     = (const float*)d_in[5];
    const float* vp_w2     = (const float*)d_in[6];
    const float* vp_b2     = (const float*)d_in[7];
    const float* gnn_wself = (const float*)d_in[8];
    const float* gnn_bself = (const float*)d_in[9];
    const float* gnn_wmsg  = (const float*)d_in[10];
    const float* gnn_bmsg  = (const float*)d_in[11];
    const float* bc_w1     = (const float*)d_in[12];
    const float* bc_b1     = (const float*)d_in[13];
    const float* bc_w2     = (const float*)d_in[14];
    const float* bc_b2     = (const float*)d_in[15];
    const float* bc_w3     = (const float*)d_in[16];
    const float* bc_b3     = (const float*)d_in[17];
    const float* cp_w1     = (const float*)d_in[18];
    const float* cp_b1     = (const float*)d_in[19];
    const float* cp_w2     = (const float*)d_in[20];
    const float* cp_b2     = (const float*)d_in[21];
    const int* edge_index  = (const int*)d_in[22];

    float* out      = (float*)d_out;
    float* out_h    = out;                                 // [N,256]
    float* out_cp   = out_h    + (size_t)NN * HID;         // [N,32]
    float* out_vlog = out_cp   + (size_t)NN * 32;          // [N,8]
    float* out_bl   = out_vlog + (size_t)NN * 8;           // [E,4]
    float* out_viol = out_bl   + (size_t)NE * 4;           // [N]

    cudaFuncSetAttribute(k_gemm, cudaFuncAttributeMaxDynamicSharedMemorySize, SMEM_PIPE);

    // resolve device-global addresses
    float *p_h0, *p_h1, *p_t, *p_z, *p_uv, *p_wmsg, *p_wself, *p_bccat;
    cudaGetSymbolAddress((void**)&p_h0,    g_h0);
    cudaGetSymbolAddress((void**)&p_h1,    g_h1);
    cudaGetSymbolAddress((void**)&p_t,     g_t);
    cudaGetSymbolAddress((void**)&p_z,     g_z);
    cudaGetSymbolAddress((void**)&p_uv,    g_uv);
    cudaGetSymbolAddress((void**)&p_wmsg,  g_wmsg_tf);
    cudaGetSymbolAddress((void**)&p_wself, g_wself_tf);
    cudaGetSymbolAddress((void**)&p_bccat, g_bcwcat_tf);

    k_prep<<<2199, 256>>>(atom_emb, vp_w1, vp_b1, vp_w2, vp_b2,
                          gnn_wmsg, gnn_bmsg, bond_emb, gnn_wself, bc_w1);
    k_node_init<<<(NN * 32 + 255) / 256, 256>>>(x, atom_emb, out_vlog);
    k_count<<<(NE + 255) / 256, 256>>>(edge_index);
    k_gemm<<<NN / 32, 256, SMEM_PIPE>>>(p_h0, p_wmsg, p_t, 3, 0);   // t0 (captured)
    k_scan1<<<98, 1024>>>();
    k_scan2<<<1, 128>>>();
    k_scan3<<<98, 1024>>>(out_viol);
    k_scatter<<<(NE + 255) / 256, 256>>>(edge_index, edge_attr);

    // layer 0: z0 = h0@Wself0; h1 = agg(z0, t0)  [rounded]
    k_gemm<<<NN / 32, 256, SMEM_PIPE>>>(p_h0, p_wself, p_z, 3, 0);
    k_agg<<<NN / 8, 256>>>(p_z, p_t, gnn_bself + 0 * HID, 0, 0, 1, p_h1);
    // layer 1
    k_gemm<<<NN / 32, 256, SMEM_PIPE>>>(p_h1, p_wmsg + 65536, p_t, 8, 0);
    k_gemm<<<NN / 32, 256, SMEM_PIPE>>>(p_h1, p_wself + 65536, p_z, 8, 0);
    k_agg<<<NN / 8, 256>>>(p_z, p_t, gnn_bself + 1 * HID, 1, 0, 1, p_h0);
    // layer 2 (damped, unrounded, straight to out_h)
    k_gemm<<<NN / 32, 256, SMEM_PIPE>>>(p_h0, p_wmsg + 2 * 65536, p_t, 8, 0);
    k_gemm<<<NN / 32, 256, SMEM_PIPE>>>(p_h0, p_wself + 2 * 65536, p_z, 8, 0);
    k_agg<<<NN / 8, 256>>>(p_z, p_t, gnn_bself + 2 * HID, 2, 1, 0, out_h);

    // bond head precompute: UV = out_h @ [W1top|W1bot]  (needs cvt)
    k_gemm<<<NN / 32, 256, SMEM_PIPE>>>(out_h, p_bccat, p_uv, 8, 1);

    k_bc<<<NE / 32, 256>>>(bc_w1, bc_b1, bc_w2, bc_b2, bc_w3, bc_b3,
                           edge_index, out_bl);
    k_cp<<<NN / 32, 256>>>(out_h, cp_w1, cp_b1, cp_w2, cp_b2, out_cp);
}

// round 14
// speedup vs baseline: 1.5891x; 1.0040x over previous
#include <cuda_runtime.h>
#include <cstdint>

#define NN 100000
#define NE 300000
#define HID 256

// ---- scratch (static device globals; allocation-free) ----
__device__ float g_h0[NN * HID];
__device__ float g_h1[NN * HID];
__device__ float g_t[NN * HID];               // t = h @ Wmsg_top (per node)
__device__ float g_z[NN * HID];               // z = h @ Wself (per node)
__device__ float g_uv[NN * HID];              // [U | V] = h_final @ [W1top|W1bot]
__device__ int   g_atype[NN];
__device__ int   g_pv[NN];
__device__ float g_deg[NN];
__device__ int   g_cnt[NN];
__device__ int   g_rowptr[NN + 1];
__device__ int   g_cur[NN];
__device__ int   g_ecol[NE];                  // CSR-slot -> source node
__device__ int   g_ebt[NE];                   // CSR-slot -> bond type
__device__ int   g_bsum[98];
__device__ int   g_boff[98];
__device__ float g_tlogits[11 * 8];
__device__ int   g_tpv[11];
__device__ float g_msgbias[3 * 5 * 256];      // folded bond-emb @ Wmsg[256:] + bmsg
__device__ float g_wmsg_tf[3 * 256 * 256];    // pre-rounded tf32 weights
__device__ float g_wself_tf[3 * 256 * 256];
__device__ float g_bcwcat_tf[256 * 256];      // [W1top | W1bot] concatenated, tf32

__device__ __forceinline__ float f2tff(float x) {
    unsigned r;
    asm("cvt.rna.tf32.f32 %0, %1;" : "=r"(r) : "f"(x));
    return __uint_as_float(r);
}
__device__ __forceinline__ float4 f2tff4(float4 v) {
    v.x = f2tff(v.x); v.y = f2tff(v.y); v.z = f2tff(v.z); v.w = f2tff(v.w);
    return v;
}

__device__ __forceinline__ void mma_tf32(float c[4],
    unsigned a0, unsigned a1, unsigned a2, unsigned a3,
    unsigned b0, unsigned b1)
{
    asm volatile(
        "mma.sync.aligned.m16n8k8.row.col.f32.tf32.tf32.f32 "
        "{%0,%1,%2,%3}, {%4,%5,%6,%7}, {%8,%9}, {%0,%1,%2,%3};"
        : "+f"(c[0]), "+f"(c[1]), "+f"(c[2]), "+f"(c[3])
        : "r"(a0), "r"(a1), "r"(a2), "r"(a3), "r"(b0), "r"(b1));
}

__device__ __forceinline__ void cpasync16(void* sptr, const void* g) {
    uint32_t sa = (uint32_t)__cvta_generic_to_shared(sptr);
    asm volatile("cp.async.cg.shared.global [%0], [%1], 16;" :: "r"(sa), "l"(g) : "memory");
}

// ============================================================
// 64-row pipelined GEMM: [64 nodes x 256] @ 512 threads (16 warps).
// Warp w owns cols [w*16, w*16+16), all 64 rows (c[4][2][4] = 32 regs).
// W L2 traffic per row is HALF of the 32-row version.
// ============================================================
#define SMEM_PIPE64 ((64 * 36 + 2 * 32 * 264) * 4)

__global__ __launch_bounds__(512, 2) void k_gemm64(
        const float* __restrict__ hin,
        const float* __restrict__ w0, float* __restrict__ out0,
        const float* __restrict__ w1, float* __restrict__ out1,
        int ksteps, int cvt, int dual)
{
    extern __shared__ float sm[];
    float (*As)[36]  = (float(*)[36])sm;
    float (*WsA)[264] = (float(*)[264])(sm + 64 * 36);
    float (*WsB)[264] = (float(*)[264])(sm + 64 * 36 + 32 * 264);

    int nb;
    const float* wtf;
    float* outp;
    if (dual) {
        int par = blockIdx.x & 1;
        nb = (blockIdx.x >> 1) * 64;
        wtf  = par ? w1 : w0;
        outp = par ? out1 : out0;
    } else {
        nb = blockIdx.x * 64;
        wtf = w0; outp = out0;
    }

    int tid = threadIdx.x;
    int warp = tid >> 5, lane = tid & 31;
    int n0 = warp * 16;
    const int lr = lane >> 2, lc = lane & 3;
    const int arow = tid >> 3, ac4 = (tid & 7) * 4;     // 64 rows x 8 float4
    const int arowi = min(nb + arow, NN - 1);           // tail clamp

    float c[4][2][4];
#pragma unroll
    for (int m = 0; m < 4; m++)
#pragma unroll
        for (int n = 0; n < 2; n++)
#pragma unroll
            for (int j = 0; j < 4; j++) c[m][n][j] = 0.f;

    // prologue
    float4 aNext = *(const float4*)&hin[(size_t)arowi * HID + ac4];
#pragma unroll
    for (int i = 0; i < 4; i++) {
        int idx = tid + 512 * i;
        int k = idx >> 6, c4 = (idx & 63) * 4;
        cpasync16(&WsA[k][c4], &wtf[(size_t)k * HID + c4]);
    }
    asm volatile("cp.async.commit_group;" ::: "memory");

    for (int kt = 0; kt < ksteps; kt++) {
        float (*Wcur)[264] = (kt & 1) ? WsB : WsA;
        float (*Wnxt)[264] = (kt & 1) ? WsA : WsB;
        float4 aCur = aNext;
        __syncthreads();
        bool next = (kt + 1 < ksteps);
        if (next) {
            int k0n = (kt + 1) * 32;
#pragma unroll
            for (int i = 0; i < 4; i++) {
                int idx = tid + 512 * i;
                int k = idx >> 6, c4 = (idx & 63) * 4;
                cpasync16(&Wnxt[k][c4], &wtf[(size_t)(k0n + k) * HID + c4]);
            }
            asm volatile("cp.async.commit_group;" ::: "memory");
            aNext = *(const float4*)&hin[(size_t)arowi * HID + k0n + ac4];
        }
        *(float4*)&As[arow][ac4] = cvt ? f2tff4(aCur) : aCur;
        if (next) asm volatile("cp.async.wait_group 1;" ::: "memory");
        else      asm volatile("cp.async.wait_group 0;" ::: "memory");
        __syncthreads();
#pragma unroll
        for (int ks = 0; ks < 4; ks++) {
            int kk = ks * 8;
            unsigned b[2][2];
#pragma unroll
            for (int n = 0; n < 2; n++) {
                int nc = n0 + n * 8 + lr;
                b[n][0] = __float_as_uint(Wcur[kk + lc][nc]);
                b[n][1] = __float_as_uint(Wcur[kk + 4 + lc][nc]);
            }
#pragma unroll
            for (int m = 0; m < 4; m++) {
                int r = m * 16 + lr;
                unsigned a0 = __float_as_uint(As[r][kk + lc]);
                unsigned a1 = __float_as_uint(As[r + 8][kk + lc]);
                unsigned a2 = __float_as_uint(As[r][kk + 4 + lc]);
                unsigned a3 = __float_as_uint(As[r + 8][kk + 4 + lc]);
#pragma unroll
                for (int n = 0; n < 2; n++)
                    mma_tf32(c[m][n], a0, a1, a2, a3, b[n][0], b[n][1]);
            }
        }
    }

    int g = lane >> 2, cc = 2 * (lane & 3);
#pragma unroll
    for (int m = 0; m < 4; m++) {
        int row0 = nb + m * 16 + g;
        int row1 = row0 + 8;
#pragma unroll
        for (int n = 0; n < 2; n++) {
            int col = n0 + n * 8 + cc;
            if (row0 < NN)
                *(float2*)&outp[(size_t)row0 * HID + col] = make_float2(c[m][n][0], c[m][n][1]);
            if (row1 < NN)
                *(float2*)&outp[(size_t)row1 * HID + col] = make_float2(c[m][n][2], c[m][n][3]);
        }
    }
}

// ============================================================
// Prep: type-pred MLP, bond-bias fold, tf32 weight pre-round
// ============================================================
__global__ void k_prep(const float* __restrict__ atom_emb,
                       const float* __restrict__ vp_w1, const float* __restrict__ vp_b1,
                       const float* __restrict__ vp_w2, const float* __restrict__ vp_b2,
                       const float* __restrict__ wmsg, const float* __restrict__ bmsg,
                       const float* __restrict__ bond_emb,
                       const float* __restrict__ wself, const float* __restrict__ bcw1)
{
    int b = blockIdx.x;
    int tid = threadIdx.x;
    if (b == 0) {
        if (tid >= 11) return;
        int t = tid;
        float z[32];
        for (int j = 0; j < 32; j++) {
            float s = vp_b1[j];
            for (int k = 0; k < 64; k++) s += atom_emb[t * 64 + k] * vp_w1[k * 32 + j];
            z[j] = fmaxf(s, 0.f);
        }
        float best = -1e30f; int bi = 0;
        for (int j = 0; j < 8; j++) {
            float s = vp_b2[j];
            for (int k = 0; k < 32; k++) s += z[k] * vp_w2[k * 8 + j];
            g_tlogits[t * 8 + j] = s;
            if (s > best) { best = s; bi = j; }
        }
        g_tpv[t] = bi + 1;
    } else if (b < 16) {
        int idx = b - 1;
        int l = idx / 5, bt = idx % 5;
        const float* w = wmsg + (size_t)l * 320 * HID;
        float s = bmsg[l * HID + tid];
#pragma unroll 8
        for (int j = 0; j < 64; j++)
            s += bond_emb[bt * 64 + j] * w[(size_t)(256 + j) * HID + tid];
        g_msgbias[(size_t)idx * 256 + tid] = s;
    } else if (b < 16 + 768) {
        int i = (b - 16) * 256 + tid;        // over 3*65536
        int l = i >> 16, rest = i & 65535;
        g_wmsg_tf[i] = f2tff(wmsg[(size_t)l * 320 * 256 + rest]);
    } else if (b < 16 + 1536) {
        int i = (b - 784) * 256 + tid;
        g_wself_tf[i] = f2tff(wself[i]);
    } else if (b < 16 + 1792) {
        int i = (b - 1552) * 256 + tid;      // over 256*256
        int k = i >> 8, n = i & 255;
        float v = (n < 128) ? bcw1[(size_t)k * 128 + n]
                            : bcw1[(size_t)(256 + k) * 128 + (n - 128)];
        g_bcwcat_tf[i] = f2tff(v);
    } else {
        int i = (b - 1808) * 256 + tid;
        if (i < NN) g_cnt[i] = 0;
    }
}

// ============================================================
// Node init: h0 stored PRE-ROUNDED to tf32 (only GEMMs consume it)
// ============================================================
__global__ void k_node_init(const float* __restrict__ x,
                            const float* __restrict__ atom_emb,
                            float* __restrict__ out_vlog)
{
    int gid = blockIdx.x * blockDim.x + threadIdx.x;
    int n = gid >> 5, lane = gid & 31;
    if (n >= NN) return;
    int at = (int)x[(size_t)n * 16];
    at = min(max(at, 0), 10);
    int pv = g_tpv[at];
    if (lane == 0) { g_atype[n] = at; g_pv[n] = pv; }
    if (lane < 8) out_vlog[(size_t)n * 8 + lane] = g_tlogits[at * 8 + lane];
#pragma unroll
    for (int r = 0; r < 8; r++) {
        int c = lane + 32 * r;
        float v;
        if (c < 64)      v = f2tff(atom_emb[at * 64 + c]);
        else if (c < 72) v = (c - 64 == pv - 1) ? 1.f : 0.f;
        else             v = 0.f;
        g_h0[(size_t)n * HID + c] = v;
    }
}

// ============================================================
// CSR build: count -> 3-phase parallel scan (+viol output) -> scatter
// ============================================================
__global__ void k_count(const int* __restrict__ edge_index)
{
    int e = blockIdx.x * blockDim.x + threadIdx.x;
    if (e < NE) atomicAdd(&g_cnt[edge_index[e]], 1);
}

__global__ void k_scan1()
{
    __shared__ int sh[32];
    int t = threadIdx.x;
    int n = blockIdx.x * 1024 + t;
    int c = (n < NN) ? g_cnt[n] : 0;
#pragma unroll
    for (int o = 16; o > 0; o >>= 1) c += __shfl_down_sync(0xffffffffu, c, o);
    if ((t & 31) == 0) sh[t >> 5] = c;
    __syncthreads();
    if (t < 32) {
        int v = sh[t];
#pragma unroll
        for (int o = 16; o > 0; o >>= 1) v += __shfl_down_sync(0xffffffffu, v, o);
        if (t == 0) g_bsum[blockIdx.x] = v;
    }
}

__global__ void k_scan2()
{
    __shared__ int sh[128];
    int t = threadIdx.x;
    int v = (t < 98) ? g_bsum[t] : 0;
    sh[t] = v;
    __syncthreads();
    for (int off = 1; off < 128; off <<= 1) {
        int u = (t >= off) ? sh[t - off] : 0;
        __syncthreads();
        sh[t] += u;
        __syncthreads();
    }
    if (t < 98) g_boff[t] = sh[t] - v;
    if (t == 97) g_rowptr[NN] = sh[97];
}

__global__ void k_scan3(float* __restrict__ out_viol)
{
    __shared__ int sh[1024];
    int t = threadIdx.x;
    int n = blockIdx.x * 1024 + t;
    int c = (n < NN) ? g_cnt[n] : 0;
    sh[t] = c;
    __syncthreads();
    for (int off = 1; off < 1024; off <<= 1) {
        int u = (t >= off) ? sh[t - off] : 0;
        __syncthreads();
        sh[t] += u;
        __syncthreads();
    }
    if (n < NN) {
        int excl = sh[t] - c + g_boff[blockIdx.x];
        g_rowptr[n] = excl;
        g_cur[n] = excl;
        g_deg[n] = (float)c;
        out_viol[n] = fmaxf((float)c - (float)g_pv[n], 0.f);
    }
}

__global__ void k_scatter(const int* __restrict__ edge_index,
                          const float* __restrict__ edge_attr)
{
    int e = blockIdx.x * blockDim.x + threadIdx.x;
    if (e < NE) {
        int pos = atomicAdd(&g_cur[edge_index[e]], 1);
        g_ecol[pos] = edge_index[NE + e];
        g_ebt[pos] = min(max((int)edge_attr[(size_t)e * 4], 0), 4);
    }
}

// ============================================================
// Aggregation (lightweight, high-occupancy): one WARP per node.
// ============================================================
__global__ __launch_bounds__(256, 5) void k_agg(
        const float* __restrict__ zb, const float* __restrict__ tb,
        const float* __restrict__ bself, int l, int damp, int rnd,
        float* __restrict__ hout)
{
    __shared__ float smb[5 * 256];
    __shared__ float sb[256];
    int tid = threadIdx.x;
    {
        const float* mb = g_msgbias + (size_t)l * 1280;
#pragma unroll
        for (int i = 0; i < 5; i++) smb[tid + 256 * i] = mb[tid + 256 * i];
        sb[tid] = bself[tid];
    }
    __syncthreads();

    int node = blockIdx.x * 8 + (tid >> 5);
    int seg = (tid & 31) * 8;
    int s = __ldg(&g_rowptr[node]);
    int e = __ldg(&g_rowptr[node + 1]);

    float4 a0 = make_float4(0.f, 0.f, 0.f, 0.f);
    float4 a1 = make_float4(0.f, 0.f, 0.f, 0.f);

    int j = s;
    for (; j + 1 < e; j += 2) {
        int c0 = __ldg(&g_ecol[j]),     bt0 = __ldg(&g_ebt[j]);
        int c1 = __ldg(&g_ecol[j + 1]), bt1 = __ldg(&g_ebt[j + 1]);
        const float* r0 = tb + (size_t)c0 * HID + seg;
        const float* r1 = tb + (size_t)c1 * HID + seg;
        float4 x0 = *(const float4*)r0;
        float4 x1 = *(const float4*)(r0 + 4);
        float4 y0 = *(const float4*)r1;
        float4 y1 = *(const float4*)(r1 + 4);
        const float* m0 = smb + bt0 * 256 + seg;
        const float* m1 = smb + bt1 * 256 + seg;
        a0.x += fmaxf(x0.x + m0[0], 0.f); a0.y += fmaxf(x0.y + m0[1], 0.f);
        a0.z += fmaxf(x0.z + m0[2], 0.f); a0.w += fmaxf(x0.w + m0[3], 0.f);
        a1.x += fmaxf(x1.x + m0[4], 0.f); a1.y += fmaxf(x1.y + m0[5], 0.f);
        a1.z += fmaxf(x1.z + m0[6], 0.f); a1.w += fmaxf(x1.w + m0[7], 0.f);
        a0.x += fmaxf(y0.x + m1[0], 0.f); a0.y += fmaxf(y0.y + m1[1], 0.f);
        a0.z += fmaxf(y0.z + m1[2], 0.f); a0.w += fmaxf(y0.w + m1[3], 0.f);
        a1.x += fmaxf(y1.x + m1[4], 0.f); a1.y += fmaxf(y1.y + m1[5], 0.f);
        a1.z += fmaxf(y1.z + m1[6], 0.f); a1.w += fmaxf(y1.w + m1[7], 0.f);
    }
    if (j < e) {
        int c0 = __ldg(&g_ecol[j]), bt0 = __ldg(&g_ebt[j]);
        const float* r0 = tb + (size_t)c0 * HID + seg;
        float4 x0 = *(const float4*)r0;
        float4 x1 = *(const float4*)(r0 + 4);
        const float* m0 = smb + bt0 * 256 + seg;
        a0.x += fmaxf(x0.x + m0[0], 0.f); a0.y += fmaxf(x0.y + m0[1], 0.f);
        a0.z += fmaxf(x0.z + m0[2], 0.f); a0.w += fmaxf(x0.w + m0[3], 0.f);
        a1.x += fmaxf(x1.x + m0[4], 0.f); a1.y += fmaxf(x1.y + m0[5], 0.f);
        a1.z += fmaxf(x1.z + m0[6], 0.f); a1.w += fmaxf(x1.w + m0[7], 0.f);
    }

    const float* zr = zb + (size_t)node * HID + seg;
    float4 z0 = *(const float4*)zr;
    float4 z1 = *(const float4*)(zr + 4);
    float sc = 1.f;
    if (damp)
        sc = 1.f / (1.f + fmaxf((float)(e - s) - (float)__ldg(&g_pv[node]), 0.f));
    float4 o0, o1;
    o0.x = fmaxf(z0.x + sb[seg + 0] + a0.x, 0.f) * sc;
    o0.y = fmaxf(z0.y + sb[seg + 1] + a0.y, 0.f) * sc;
    o0.z = fmaxf(z0.z + sb[seg + 2] + a0.z, 0.f) * sc;
    o0.w = fmaxf(z0.w + sb[seg + 3] + a0.w, 0.f) * sc;
    o1.x = fmaxf(z1.x + sb[seg + 4] + a1.x, 0.f) * sc;
    o1.y = fmaxf(z1.y + sb[seg + 5] + a1.y, 0.f) * sc;
    o1.z = fmaxf(z1.z + sb[seg + 6] + a1.z, 0.f) * sc;
    o1.w = fmaxf(z1.w + sb[seg + 7] + a1.w, 0.f) * sc;
    if (rnd) { o0 = f2tff4(o0); o1 = f2tff4(o1); }
    float* op = hout + (size_t)node * HID + seg;
    *(float4*)op = o0;
    *(float4*)(op + 4) = o1;
}

// ============================================================
// Bond head: stage1 = gather relu(U[row]+V[col]+pv terms+b1),
// stages 2-3 SIMT. No MMA here.
// ============================================================
__global__ __launch_bounds__(256) void k_bc(
        const float* __restrict__ w1, const float* __restrict__ b1,
        const float* __restrict__ w2, const float* __restrict__ b2,
        const float* __restrict__ w3, const float* __restrict__ b3,
        const int* __restrict__ edge_index, float* __restrict__ out_bl)
{
    __shared__ float T1[32][132];
    __shared__ float T2[32][65];
    __shared__ float Ws[32][68];
    __shared__ float s_wpr[128], s_wpc[128], s_bb[128];
    __shared__ int s_row[32], s_col[32], s_atr[32], s_atc[32];
    __shared__ float s_pvr[32], s_pvc[32];
    int tid = threadIdx.x;
    int eb = blockIdx.x * 32;
    if (tid < 32) {
        int e = eb + tid;
        int r = edge_index[e], c = edge_index[NE + e];
        s_row[tid] = r; s_col[tid] = c;
        s_pvr[tid] = (float)g_pv[r]; s_pvc[tid] = (float)g_pv[c];
        s_atr[tid] = g_atype[r];     s_atc[tid] = g_atype[c];
    }
    if (tid < 128) {
        s_wpr[tid] = w1[512 * 128 + tid];
        s_wpc[tid] = w1[513 * 128 + tid];
        s_bb[tid]  = b1[tid];
    }
    __syncthreads();

    int warp = tid >> 5, lane = tid & 31;
    int o = lane * 4;
#pragma unroll
    for (int it = 0; it < 4; it++) {
        int e = warp * 4 + it;
        float4 u = *(const float4*)&g_uv[(size_t)s_row[e] * 256 + o];
        float4 v = *(const float4*)&g_uv[(size_t)s_col[e] * 256 + 128 + o];
        float pr = s_pvr[e], pc = s_pvc[e];
        float4 t;
        t.x = fmaxf(u.x + v.x + pr * s_wpr[o]     + pc * s_wpc[o]     + s_bb[o],     0.f);
        t.y = fmaxf(u.y + v.y + pr * s_wpr[o + 1] + pc * s_wpc[o + 1] + s_bb[o + 1], 0.f);
        t.z = fmaxf(u.z + v.z + pr * s_wpr[o + 2] + pc * s_wpc[o + 2] + s_bb[o + 2], 0.f);
        t.w = fmaxf(u.w + v.w + pr * s_wpr[o + 3] + pc * s_wpc[o + 3] + s_bb[o + 3], 0.f);
        *(float4*)&T1[e][o] = t;
    }
    __syncthreads();

    // ---- stage 2: [32 x 64], K=128 (SIMT) ----
    float acc2[2][4];
#pragma unroll
    for (int i = 0; i < 2; i++)
#pragma unroll
        for (int j = 0; j < 4; j++) acc2[i][j] = 0.f;
    const int tx2 = tid & 15, ty2 = tid >> 4;
    for (int kt = 0; kt < 4; kt++) {
        int k0 = kt * 32;
#pragma unroll
        for (int i = 0; i < 2; i++) {
            int idx = tid + 256 * i;
            int k = idx >> 4, c4 = (idx & 15) * 4;
            *(float4*)&Ws[k][c4] = *(const float4*)&w2[(size_t)(k0 + k) * 64 + c4];
        }
        __syncthreads();
#pragma unroll
        for (int kk = 0; kk < 32; kk++) {
            float a0 = T1[ty2 * 2][k0 + kk];
            float a1 = T1[ty2 * 2 + 1][k0 + kk];
            float4 w = *(const float4*)&Ws[kk][tx2 * 4];
            acc2[0][0] += a0 * w.x; acc2[0][1] += a0 * w.y;
            acc2[0][2] += a0 * w.z; acc2[0][3] += a0 * w.w;
            acc2[1][0] += a1 * w.x; acc2[1][1] += a1 * w.y;
            acc2[1][2] += a1 * w.z; acc2[1][3] += a1 * w.w;
        }
        __syncthreads();
    }
#pragma unroll
    for (int i = 0; i < 2; i++) {
        int e = ty2 * 2 + i;
#pragma unroll
        for (int j = 0; j < 4; j++) {
            int oo = tx2 * 4 + j;
            T2[e][oo] = fmaxf(acc2[i][j] + __ldg(&b2[oo]), 0.f);
        }
    }
    __syncthreads();

    // ---- stage 3: [32 x 4], K=64, + chemical penalties ----
    if (tid < 128) {
        int e = tid >> 2, oo = tid & 3;
        float s = __ldg(&b3[oo]);
#pragma unroll
        for (int k = 0; k < 64; k++) s += T2[e][k] * __ldg(&w3[k * 4 + oo]);
        int ar = s_atr[e], ac = s_atc[e];
        float pr = s_pvr[e], pc = s_pvc[e];
        bool hal = (ar == 4) || (ar == 5) || (ac == 4) || (ac == 5);
        bool l1 = (pr <= 1.f) || (pc <= 1.f);
        bool l2 = (pr <= 2.f) || (pc <= 2.f);
        float pen = 0.f;
        if (oo >= 1) { if (hal) pen -= 100.f; if (l1) pen -= 50.f; }
        if (oo == 2) { if (l2) pen -= 50.f; }
        out_bl[(size_t)(eb + e) * 4 + oo] = s + pen;
    }
}

// ============================================================
// Chem head (SIMT; small)
// ============================================================
__global__ __launch_bounds__(256) void k_cp(const float* __restrict__ hfin,
        const float* __restrict__ w1, const float* __restrict__ b1,
        const float* __restrict__ w2, const float* __restrict__ b2,
        float* __restrict__ out_cp)
{
    __shared__ float As[32][36];
    __shared__ float Ws[32][132];
    __shared__ float T1[32][129];
    int tid = threadIdx.x;
    int nb = blockIdx.x * 32;
    float acc[4][4];
#pragma unroll
    for (int i = 0; i < 4; i++)
#pragma unroll
        for (int j = 0; j < 4; j++) acc[i][j] = 0.f;
    const int tx = tid & 31, ty = tid >> 5;
    const int arow = tid >> 3, ac4 = (tid & 7) * 4;
    for (int kt = 0; kt < 8; kt++) {
        int k0 = kt * 32;
        *(float4*)&As[arow][ac4] =
            *(const float4*)&hfin[(size_t)(nb + arow) * HID + k0 + ac4];
#pragma unroll
        for (int i = 0; i < 4; i++) {
            int idx = tid + 256 * i;
            int k = idx >> 5, c4 = (idx & 31) * 4;
            *(float4*)&Ws[k][c4] = *(const float4*)&w1[(size_t)(k0 + k) * 128 + c4];
        }
        __syncthreads();
#pragma unroll
        for (int kk = 0; kk < 32; kk++) {
            float a[4];
#pragma unroll
            for (int i = 0; i < 4; i++) a[i] = As[ty * 4 + i][kk];
            float4 w = *(const float4*)&Ws[kk][tx * 4];
#pragma unroll
            for (int i = 0; i < 4; i++) {
                acc[i][0] += a[i] * w.x; acc[i][1] += a[i] * w.y;
                acc[i][2] += a[i] * w.z; acc[i][3] += a[i] * w.w;
            }
        }
        __syncthreads();
    }
#pragma unroll
    for (int i = 0; i < 4; i++) {
        int e = ty * 4 + i;
#pragma unroll
        for (int j = 0; j < 4; j++) {
            int o = tx * 4 + j;
            T1[e][o] = fmaxf(acc[i][j] + __ldg(&b1[o]), 0.f);
        }
    }
    __syncthreads();

    float acc2[4] = {0.f, 0.f, 0.f, 0.f};
    const int tx2 = tid & 7, ty2 = tid >> 3;
    for (int kt = 0; kt < 4; kt++) {
        int k0 = kt * 32;
        {
            int k = tid >> 3, c4 = (tid & 7) * 4;
            *(float4*)&Ws[k][c4] = *(const float4*)&w2[(size_t)(k0 + k) * 32 + c4];
        }
        __syncthreads();
#pragma unroll
        for (int kk = 0; kk < 32; kk++) {
            float a = T1[ty2][k0 + kk];
            float4 w = *(const float4*)&Ws[kk][tx2 * 4];
            acc2[0] += a * w.x; acc2[1] += a * w.y;
            acc2[2] += a * w.z; acc2[3] += a * w.w;
        }
        __syncthreads();
    }
#pragma unroll
    for (int j = 0; j < 4; j++) {
        int o = tx2 * 4 + j;
        out_cp[(size_t)(nb + ty2) * 32 + o] = acc2[j] + __ldg(&b2[o]);
    }
}

// ============================================================
extern "C" void kernel_launch(void* const* d_in, const int* in_sizes, int n_in,
                              void* d_out, int out_size)
{
    (void)in_sizes; (void)n_in; (void)out_size;
    const float* x         = (const float*)d_in[0];
    const float* edge_attr = (const float*)d_in[1];
    const float* atom_emb  = (const float*)d_in[2];
    const float* bond_emb  = (const float*)d_in[3];
    const float* vp_w1     = (const float*)d_in[4];
    const float* vp_b1     = (const float*)d_in[5];
    const float* vp_w2     = (const float*)d_in[6];
    const float* vp_b2     = (const float*)d_in[7];
    const float* gnn_wself = (const float*)d_in[8];
    const float* gnn_bself = (const float*)d_in[9];
    const float* gnn_wmsg  = (const float*)d_in[10];
    const float* gnn_bmsg  = (const float*)d_in[11];
    const float* bc_w1     = (const float*)d_in[12];
    const float* bc_b1     = (const float*)d_in[13];
    const float* bc_w2     = (const float*)d_in[14];
    const float* bc_b2     = (const float*)d_in[15];
    const float* bc_w3     = (const float*)d_in[16];
    const float* bc_b3     = (const float*)d_in[17];
    const float* cp_w1     = (const float*)d_in[18];
    const float* cp_b1     = (const float*)d_in[19];
    const float* cp_w2     = (const float*)d_in[20];
    const float* cp_b2     = (const float*)d_in[21];
    const int* edge_index  = (const int*)d_in[22];

    float* out      = (float*)d_out;
    float* out_h    = out;                                 // [N,256]
    float* out_cp   = out_h    + (size_t)NN * HID;         // [N,32]
    float* out_vlog = out_cp   + (size_t)NN * 32;          // [N,8]
    float* out_bl   = out_vlog + (size_t)NN * 8;           // [E,4]
    float* out_viol = out_bl   + (size_t)NE * 4;           // [N]

    cudaFuncSetAttribute(k_gemm64, cudaFuncAttributeMaxDynamicSharedMemorySize, SMEM_PIPE64);

    // resolve device-global addresses
    float *p_h0, *p_h1, *p_t, *p_z, *p_uv, *p_wmsg, *p_wself, *p_bccat;
    cudaGetSymbolAddress((void**)&p_h0,    g_h0);
    cudaGetSymbolAddress((void**)&p_h1,    g_h1);
    cudaGetSymbolAddress((void**)&p_t,     g_t);
    cudaGetSymbolAddress((void**)&p_z,     g_z);
    cudaGetSymbolAddress((void**)&p_uv,    g_uv);
    cudaGetSymbolAddress((void**)&p_wmsg,  g_wmsg_tf);
    cudaGetSymbolAddress((void**)&p_wself, g_wself_tf);
    cudaGetSymbolAddress((void**)&p_bccat, g_bcwcat_tf);

    const int GB = (NN + 63) / 64;            // 1563 blocks per matrix

    k_prep<<<2199, 256>>>(atom_emb, vp_w1, vp_b1, vp_w2, vp_b2,
                          gnn_wmsg, gnn_bmsg, bond_emb, gnn_wself, bc_w1);
    k_node_init<<<(NN * 32 + 255) / 256, 256>>>(x, atom_emb, out_vlog);
    k_count<<<(NE + 255) / 256, 256>>>(edge_index);
    // layer-0 dual GEMM: t0 = h0@Wmsg0, z0 = h0@Wself0   (captured by ncu)
    k_gemm64<<<2 * GB, 512, SMEM_PIPE64>>>(p_h0, p_wmsg, p_t, p_wself, p_z, 3, 0, 1);
    k_scan1<<<98, 1024>>>();
    k_scan2<<<1, 128>>>();
    k_scan3<<<98, 1024>>>(out_viol);
    k_scatter<<<(NE + 255) / 256, 256>>>(edge_index, edge_attr);

    // layer 0 aggregate: h1 = agg(z0, t0)  [rounded]
    k_agg<<<NN / 8, 256>>>(p_z, p_t, gnn_bself + 0 * HID, 0, 0, 1, p_h1);
    // layer 1
    k_gemm64<<<2 * GB, 512, SMEM_PIPE64>>>(p_h1, p_wmsg + 65536, p_t,
                                           p_wself + 65536, p_z, 8, 0, 1);
    k_agg<<<NN / 8, 256>>>(p_z, p_t, gnn_bself + 1 * HID, 1, 0, 1, p_h0);
    // layer 2 (damped, unrounded, straight to out_h)
    k_gemm64<<<2 * GB, 512, SMEM_PIPE64>>>(p_h0, p_wmsg + 2 * 65536, p_t,
                                           p_wself + 2 * 65536, p_z, 8, 0, 1);
    k_agg<<<NN / 8, 256>>>(p_z, p_t, gnn_bself + 2 * HID, 2, 1, 0, out_h);

    // bond head precompute: UV = out_h @ [W1top|W1bot]  (needs cvt)
    k_gemm64<<<GB, 512, SMEM_PIPE64>>>(out_h, p_bccat, p_uv, nullptr, nullptr, 8, 1, 0);

    k_bc<<<NE / 32, 256>>>(bc_w1, bc_b1, bc_w2, bc_b2, bc_w3, bc_b3,
                           edge_index, out_bl);
    k_cp<<<NN / 32, 256>>>(out_h, cp_w1, cp_b1, cp_w2, cp_b2, out_cp);
}

// round 15
// speedup vs baseline: 1.9378x; 1.2195x over previous
#include <cuda_runtime.h>
#include <cuda_fp16.h>
#include <cstdint>

#define NN 100000
#define NE 300000
#define HID 256

// ---- scratch (static device globals; allocation-free) ----
__device__ __half g_h0h[NN * HID];            // h (fp16) ping
__device__ __half g_h1h[NN * HID];            // h (fp16) pong
__device__ float g_t[NN * HID];               // t = h @ Wmsg_top (fp32)
__device__ float g_z[NN * HID];               // z = h @ Wself (fp32)
__device__ float g_uv[NN * HID];              // [U | V] (fp32)
__device__ int   g_atype[NN];
__device__ int   g_pv[NN];
__device__ float g_deg[NN];
__device__ int   g_cnt[NN];
__device__ int   g_rowptr[NN + 1];
__device__ int   g_cur[NN];
__device__ int   g_ecol[NE];
__device__ int   g_ebt[NE];
__device__ int   g_bsum[98];
__device__ int   g_boff[98];
__device__ float g_tlogits[11 * 8];
__device__ int   g_tpv[11];
__device__ float g_msgbias[3 * 5 * 256];
__device__ __half2 g_wmsg_h[3 * 128 * 256];   // k-pair packed fp16 weights
__device__ __half2 g_wself_h[3 * 128 * 256];
__device__ __half2 g_bccat_h[128 * 256];

__device__ __forceinline__ void mma_f16(float c[4],
    unsigned a0, unsigned a1, unsigned a2, unsigned a3,
    unsigned b0, unsigned b1)
{
    asm volatile(
        "mma.sync.aligned.m16n8k16.row.col.f32.f16.f16.f32 "
        "{%0,%1,%2,%3}, {%4,%5,%6,%7}, {%8,%9}, {%0,%1,%2,%3};"
        : "+f"(c[0]), "+f"(c[1]), "+f"(c[2]), "+f"(c[3])
        : "r"(a0), "r"(a1), "r"(a2), "r"(a3), "r"(b0), "r"(b1));
}

__device__ __forceinline__ void cpasync16(void* sptr, const void* g) {
    uint32_t sa = (uint32_t)__cvta_generic_to_shared(sptr);
    asm volatile("cp.async.cg.shared.global [%0], [%1], 16;" :: "r"(sa), "l"(g) : "memory");
}

// ============================================================
// 64-row fp16 pipelined GEMM: [64 nodes x 256] @ 512 threads.
// Warp w owns cols [w*16, w*16+16); c[4][2][4] fp32 accum.
// A: half [64][40]; W: half2 [16][264] x2 (k-pair packed).
// ============================================================
#define A_STRIDE 40
#define W_STRIDE 264
#define SMEM_F16 (64 * A_STRIDE * 2 + 2 * 16 * W_STRIDE * 4)

__global__ __launch_bounds__(512, 2) void k_gemm64(
        const __half* __restrict__ hin,
        const __half2* __restrict__ w0, float* __restrict__ out0,
        const __half2* __restrict__ w1, float* __restrict__ out1,
        int ksteps, int dual)
{
    extern __shared__ char smraw[];
    __half (*As)[A_STRIDE] = (__half(*)[A_STRIDE])smraw;
    __half2 (*WsA)[W_STRIDE] = (__half2(*)[W_STRIDE])(smraw + 64 * A_STRIDE * 2);
    __half2 (*WsB)[W_STRIDE] = (__half2(*)[W_STRIDE])(smraw + 64 * A_STRIDE * 2 + 16 * W_STRIDE * 4);

    int nb;
    const __half2* wtf;
    float* outp;
    if (dual) {
        int par = blockIdx.x & 1;
        nb = (blockIdx.x >> 1) * 64;
        wtf  = par ? w1 : w0;
        outp = par ? out1 : out0;
    } else {
        nb = blockIdx.x * 64;
        wtf = w0; outp = out0;
    }

    int tid = threadIdx.x;
    int warp = tid >> 5, lane = tid & 31;
    int n0 = warp * 16;
    const int lr = lane >> 2, lc = lane & 3;
    const int arow = tid >> 3, ah4 = (tid & 7) * 4;     // 64 rows x 8 threads x 4 halves
    const int arowi = min(nb + arow, NN - 1);

    float c[4][2][4];
#pragma unroll
    for (int m = 0; m < 4; m++)
#pragma unroll
        for (int n = 0; n < 2; n++)
#pragma unroll
            for (int j = 0; j < 4; j++) c[m][n][j] = 0.f;

    // prologue: W tile 0 (16 rows x 256 half2) via cp.async; A tile 0 to regs
    uint2 aNext = *(const uint2*)&hin[(size_t)arowi * HID + ah4];
#pragma unroll
    for (int i = 0; i < 2; i++) {
        int idx = tid + 512 * i;                // 1024 chunks of 4 half2
        int r = idx >> 6, c4 = (idx & 63) * 4;
        cpasync16(&WsA[r][c4], &wtf[(size_t)r * 256 + c4]);
    }
    asm volatile("cp.async.commit_group;" ::: "memory");

    for (int kt = 0; kt < ksteps; kt++) {
        __half2 (*Wcur)[W_STRIDE] = (kt & 1) ? WsB : WsA;
        __half2 (*Wnxt)[W_STRIDE] = (kt & 1) ? WsA : WsB;
        uint2 aCur = aNext;
        __syncthreads();
        bool next = (kt + 1 < ksteps);
        if (next) {
            int kp0 = (kt + 1) * 16;
#pragma unroll
            for (int i = 0; i < 2; i++) {
                int idx = tid + 512 * i;
                int r = idx >> 6, c4 = (idx & 63) * 4;
                cpasync16(&Wnxt[r][c4], &wtf[(size_t)(kp0 + r) * 256 + c4]);
            }
            asm volatile("cp.async.commit_group;" ::: "memory");
            aNext = *(const uint2*)&hin[(size_t)arowi * HID + (kt + 1) * 32 + ah4];
        }
        *(uint2*)&As[arow][ah4] = aCur;
        if (next) asm volatile("cp.async.wait_group 1;" ::: "memory");
        else      asm volatile("cp.async.wait_group 0;" ::: "memory");
        __syncthreads();
#pragma unroll
        for (int ks = 0; ks < 2; ks++) {
            int kb = ks * 16;                   // A half-col base
            int wb = ks * 8;                    // W kp-row base
            unsigned b[2][2];
#pragma unroll
            for (int n = 0; n < 2; n++) {
                int nc = n0 + n * 8 + lr;
                b[n][0] = *(const unsigned*)&Wcur[wb + lc][nc];
                b[n][1] = *(const unsigned*)&Wcur[wb + lc + 4][nc];
            }
#pragma unroll
            for (int m = 0; m < 4; m++) {
                int r = m * 16 + lr;
                unsigned a0 = *(const unsigned*)&As[r][kb + 2 * lc];
                unsigned a1 = *(const unsigned*)&As[r + 8][kb + 2 * lc];
                unsigned a2 = *(const unsigned*)&As[r][kb + 2 * lc + 8];
                unsigned a3 = *(const unsigned*)&As[r + 8][kb + 2 * lc + 8];
#pragma unroll
                for (int n = 0; n < 2; n++)
                    mma_f16(c[m][n], a0, a1, a2, a3, b[n][0], b[n][1]);
            }
        }
    }

    int g = lane >> 2, cc = 2 * (lane & 3);
#pragma unroll
    for (int m = 0; m < 4; m++) {
        int row0 = nb + m * 16 + g;
        int row1 = row0 + 8;
#pragma unroll
        for (int n = 0; n < 2; n++) {
            int col = n0 + n * 8 + cc;
            if (row0 < NN)
                *(float2*)&outp[(size_t)row0 * HID + col] = make_float2(c[m][n][0], c[m][n][1]);
            if (row1 < NN)
                *(float2*)&outp[(size_t)row1 * HID + col] = make_float2(c[m][n][2], c[m][n][3]);
        }
    }
}

// ============================================================
// Prep: type-pred MLP (b0), bond-bias fold (1..15), fp16 weight
// packing (wmsg 16..399, wself 400..783, bccat 784..911), cnt zero
// ============================================================
__global__ void k_prep(const float* __restrict__ atom_emb,
                       const float* __restrict__ vp_w1, const float* __restrict__ vp_b1,
                       const float* __restrict__ vp_w2, const float* __restrict__ vp_b2,
                       const float* __restrict__ wmsg, const float* __restrict__ bmsg,
                       const float* __restrict__ bond_emb,
                       const float* __restrict__ wself, const float* __restrict__ bcw1)
{
    int b = blockIdx.x;
    int tid = threadIdx.x;
    if (b == 0) {
        if (tid >= 11) return;
        int t = tid;
        float z[32];
        for (int j = 0; j < 32; j++) {
            float s = vp_b1[j];
            for (int k = 0; k < 64; k++) s += atom_emb[t * 64 + k] * vp_w1[k * 32 + j];
            z[j] = fmaxf(s, 0.f);
        }
        float best = -1e30f; int bi = 0;
        for (int j = 0; j < 8; j++) {
            float s = vp_b2[j];
            for (int k = 0; k < 32; k++) s += z[k] * vp_w2[k * 8 + j];
            g_tlogits[t * 8 + j] = s;
            if (s > best) { best = s; bi = j; }
        }
        g_tpv[t] = bi + 1;
    } else if (b < 16) {
        int idx = b - 1;
        int l = idx / 5, bt = idx % 5;
        const float* w = wmsg + (size_t)l * 320 * HID;
        float s = bmsg[l * HID + tid];
#pragma unroll 8
        for (int j = 0; j < 64; j++)
            s += bond_emb[bt * 64 + j] * w[(size_t)(256 + j) * HID + tid];
        g_msgbias[(size_t)idx * 256 + tid] = s;
    } else if (b < 400) {
        int i = (b - 16) * 256 + tid;          // over 3*32768
        int l = i >> 15, rest = i & 32767;
        int kp = rest >> 8, n = rest & 255;
        const float* w = wmsg + (size_t)l * 320 * 256;
        g_wmsg_h[i] = __halves2half2(
            __float2half_rn(w[(size_t)(2 * kp) * 256 + n]),
            __float2half_rn(w[(size_t)(2 * kp + 1) * 256 + n]));
    } else if (b < 784) {
        int i = (b - 400) * 256 + tid;
        int l = i >> 15, rest = i & 32767;
        int kp = rest >> 8, n = rest & 255;
        const float* w = wself + (size_t)l * 65536;
        g_wself_h[i] = __halves2half2(
            __float2half_rn(w[(size_t)(2 * kp) * 256 + n]),
            __float2half_rn(w[(size_t)(2 * kp + 1) * 256 + n]));
    } else if (b < 912) {
        int i = (b - 784) * 256 + tid;         // over 128*256
        int kp = i >> 8, n = i & 255;
        float lo = (n < 128) ? bcw1[(size_t)(2 * kp) * 128 + n]
                             : bcw1[(size_t)(256 + 2 * kp) * 128 + (n - 128)];
        float hi = (n < 128) ? bcw1[(size_t)(2 * kp + 1) * 128 + n]
                             : bcw1[(size_t)(256 + 2 * kp + 1) * 128 + (n - 128)];
        g_bccat_h[i] = __halves2half2(__float2half_rn(lo), __float2half_rn(hi));
    } else {
        int i = (b - 912) * 256 + tid;
        if (i < NN) g_cnt[i] = 0;
    }
}

// ============================================================
// Node init: h0 stored as fp16 (only GEMMs consume it)
// ============================================================
__global__ void k_node_init(const float* __restrict__ x,
                            const float* __restrict__ atom_emb,
                            float* __restrict__ out_vlog)
{
    int gid = blockIdx.x * blockDim.x + threadIdx.x;
    int n = gid >> 5, lane = gid & 31;
    if (n >= NN) return;
    int at = (int)x[(size_t)n * 16];
    at = min(max(at, 0), 10);
    int pv = g_tpv[at];
    if (lane == 0) { g_atype[n] = at; g_pv[n] = pv; }
    if (lane < 8) out_vlog[(size_t)n * 8 + lane] = g_tlogits[at * 8 + lane];
#pragma unroll
    for (int r = 0; r < 8; r++) {
        int c = lane + 32 * r;
        float v;
        if (c < 64)      v = atom_emb[at * 64 + c];
        else if (c < 72) v = (c - 64 == pv - 1) ? 1.f : 0.f;
        else             v = 0.f;
        g_h0h[(size_t)n * HID + c] = __float2half_rn(v);
    }
}

// ============================================================
// CSR build
// ============================================================
__global__ void k_count(const int* __restrict__ edge_index)
{
    int e = blockIdx.x * blockDim.x + threadIdx.x;
    if (e < NE) atomicAdd(&g_cnt[edge_index[e]], 1);
}

__global__ void k_scan1()
{
    __shared__ int sh[32];
    int t = threadIdx.x;
    int n = blockIdx.x * 1024 + t;
    int c = (n < NN) ? g_cnt[n] : 0;
#pragma unroll
    for (int o = 16; o > 0; o >>= 1) c += __shfl_down_sync(0xffffffffu, c, o);
    if ((t & 31) == 0) sh[t >> 5] = c;
    __syncthreads();
    if (t < 32) {
        int v = sh[t];
#pragma unroll
        for (int o = 16; o > 0; o >>= 1) v += __shfl_down_sync(0xffffffffu, v, o);
        if (t == 0) g_bsum[blockIdx.x] = v;
    }
}

__global__ void k_scan2()
{
    __shared__ int sh[128];
    int t = threadIdx.x;
    int v = (t < 98) ? g_bsum[t] : 0;
    sh[t] = v;
    __syncthreads();
    for (int off = 1; off < 128; off <<= 1) {
        int u = (t >= off) ? sh[t - off] : 0;
        __syncthreads();
        sh[t] += u;
        __syncthreads();
    }
    if (t < 98) g_boff[t] = sh[t] - v;
    if (t == 97) g_rowptr[NN] = sh[97];
}

__global__ void k_scan3(float* __restrict__ out_viol)
{
    __shared__ int sh[1024];
    int t = threadIdx.x;
    int n = blockIdx.x * 1024 + t;
    int c = (n < NN) ? g_cnt[n] : 0;
    sh[t] = c;
    __syncthreads();
    for (int off = 1; off < 1024; off <<= 1) {
        int u = (t >= off) ? sh[t - off] : 0;
        __syncthreads();
        sh[t] += u;
        __syncthreads();
    }
    if (n < NN) {
        int excl = sh[t] - c + g_boff[blockIdx.x];
        g_rowptr[n] = excl;
        g_cur[n] = excl;
        g_deg[n] = (float)c;
        out_viol[n] = fmaxf((float)c - (float)g_pv[n], 0.f);
    }
}

__global__ void k_scatter(const int* __restrict__ edge_index,
                          const float* __restrict__ edge_attr)
{
    int e = blockIdx.x * blockDim.x + threadIdx.x;
    if (e < NE) {
        int pos = atomicAdd(&g_cur[edge_index[e]], 1);
        g_ecol[pos] = edge_index[NE + e];
        g_ebt[pos] = min(max((int)edge_attr[(size_t)e * 4], 0), 4);
    }
}

// ============================================================
// Aggregation: one WARP per node; fp32 math on t/z; writes fp16 h
// (and fp32 out_h when damp).
// ============================================================
__global__ __launch_bounds__(256, 5) void k_agg(
        const float* __restrict__ zb, const float* __restrict__ tb,
        const float* __restrict__ bself, int l, int damp,
        float* __restrict__ outf, __half* __restrict__ outh)
{
    __shared__ float smb[5 * 256];
    __shared__ float sb[256];
    int tid = threadIdx.x;
    {
        const float* mb = g_msgbias + (size_t)l * 1280;
#pragma unroll
        for (int i = 0; i < 5; i++) smb[tid + 256 * i] = mb[tid + 256 * i];
        sb[tid] = bself[tid];
    }
    __syncthreads();

    int node = blockIdx.x * 8 + (tid >> 5);
    int seg = (tid & 31) * 8;
    int s = __ldg(&g_rowptr[node]);
    int e = __ldg(&g_rowptr[node + 1]);

    float4 a0 = make_float4(0.f, 0.f, 0.f, 0.f);
    float4 a1 = make_float4(0.f, 0.f, 0.f, 0.f);

    int j = s;
    for (; j + 1 < e; j += 2) {
        int c0 = __ldg(&g_ecol[j]),     bt0 = __ldg(&g_ebt[j]);
        int c1 = __ldg(&g_ecol[j + 1]), bt1 = __ldg(&g_ebt[j + 1]);
        const float* r0 = tb + (size_t)c0 * HID + seg;
        const float* r1 = tb + (size_t)c1 * HID + seg;
        float4 x0 = *(const float4*)r0;
        float4 x1 = *(const float4*)(r0 + 4);
        float4 y0 = *(const float4*)r1;
        float4 y1 = *(const float4*)(r1 + 4);
        const float* m0 = smb + bt0 * 256 + seg;
        const float* m1 = smb + bt1 * 256 + seg;
        a0.x += fmaxf(x0.x + m0[0], 0.f); a0.y += fmaxf(x0.y + m0[1], 0.f);
        a0.z += fmaxf(x0.z + m0[2], 0.f); a0.w += fmaxf(x0.w + m0[3], 0.f);
        a1.x += fmaxf(x1.x + m0[4], 0.f); a1.y += fmaxf(x1.y + m0[5], 0.f);
        a1.z += fmaxf(x1.z + m0[6], 0.f); a1.w += fmaxf(x1.w + m0[7], 0.f);
        a0.x += fmaxf(y0.x + m1[0], 0.f); a0.y += fmaxf(y0.y + m1[1], 0.f);
        a0.z += fmaxf(y0.z + m1[2], 0.f); a0.w += fmaxf(y0.w + m1[3], 0.f);
        a1.x += fmaxf(y1.x + m1[4], 0.f); a1.y += fmaxf(y1.y + m1[5], 0.f);
        a1.z += fmaxf(y1.z + m1[6], 0.f); a1.w += fmaxf(y1.w + m1[7], 0.f);
    }
    if (j < e) {
        int c0 = __ldg(&g_ecol[j]), bt0 = __ldg(&g_ebt[j]);
        const float* r0 = tb + (size_t)c0 * HID + seg;
        float4 x0 = *(const float4*)r0;
        float4 x1 = *(const float4*)(r0 + 4);
        const float* m0 = smb + bt0 * 256 + seg;
        a0.x += fmaxf(x0.x + m0[0], 0.f); a0.y += fmaxf(x0.y + m0[1], 0.f);
        a0.z += fmaxf(x0.z + m0[2], 0.f); a0.w += fmaxf(x0.w + m0[3], 0.f);
        a1.x += fmaxf(x1.x + m0[4], 0.f); a1.y += fmaxf(x1.y + m0[5], 0.f);
        a1.z += fmaxf(x1.z + m0[6], 0.f); a1.w += fmaxf(x1.w + m0[7], 0.f);
    }

    const float* zr = zb + (size_t)node * HID + seg;
    float4 z0 = *(const float4*)zr;
    float4 z1 = *(const float4*)(zr + 4);
    float sc = 1.f;
    if (damp)
        sc = 1.f / (1.f + fmaxf((float)(e - s) - (float)__ldg(&g_pv[node]), 0.f));
    float4 o0, o1;
    o0.x = fmaxf(z0.x + sb[seg + 0] + a0.x, 0.f) * sc;
    o0.y = fmaxf(z0.y + sb[seg + 1] + a0.y, 0.f) * sc;
    o0.z = fmaxf(z0.z + sb[seg + 2] + a0.z, 0.f) * sc;
    o0.w = fmaxf(z0.w + sb[seg + 3] + a0.w, 0.f) * sc;
    o1.x = fmaxf(z1.x + sb[seg + 4] + a1.x, 0.f) * sc;
    o1.y = fmaxf(z1.y + sb[seg + 5] + a1.y, 0.f) * sc;
    o1.z = fmaxf(z1.z + sb[seg + 6] + a1.z, 0.f) * sc;
    o1.w = fmaxf(z1.w + sb[seg + 7] + a1.w, 0.f) * sc;
    if (damp) {
        float* op = outf + (size_t)node * HID + seg;
        *(float4*)op = o0;
        *(float4*)(op + 4) = o1;
    }
    __half2 hp[4];
    hp[0] = __floats2half2_rn(o0.x, o0.y);
    hp[1] = __floats2half2_rn(o0.z, o0.w);
    hp[2] = __floats2half2_rn(o1.x, o1.y);
    hp[3] = __floats2half2_rn(o1.z, o1.w);
    *(uint4*)(outh + (size_t)node * HID + seg) = *(uint4*)hp;
}

// ============================================================
// Bond head: stage1 = gather relu(U[row]+V[col]+pv terms+b1),
// stages 2-3 SIMT.
// ============================================================
__global__ __launch_bounds__(256) void k_bc(
        const float* __restrict__ w1, const float* __restrict__ b1,
        const float* __restrict__ w2, const float* __restrict__ b2,
        const float* __restrict__ w3, const float* __restrict__ b3,
        const int* __restrict__ edge_index, float* __restrict__ out_bl)
{
    __shared__ float T1[32][132];
    __shared__ float T2[32][65];
    __shared__ float Ws[32][68];
    __shared__ float s_wpr[128], s_wpc[128], s_bb[128];
    __shared__ int s_row[32], s_col[32], s_atr[32], s_atc[32];
    __shared__ float s_pvr[32], s_pvc[32];
    int tid = threadIdx.x;
    int eb = blockIdx.x * 32;
    if (tid < 32) {
        int e = eb + tid;
        int r = edge_index[e], c = edge_index[NE + e];
        s_row[tid] = r; s_col[tid] = c;
        s_pvr[tid] = (float)g_pv[r]; s_pvc[tid] = (float)g_pv[c];
        s_atr[tid] = g_atype[r];     s_atc[tid] = g_atype[c];
    }
    if (tid < 128) {
        s_wpr[tid] = w1[512 * 128 + tid];
        s_wpc[tid] = w1[513 * 128 + tid];
        s_bb[tid]  = b1[tid];
    }
    __syncthreads();

    int warp = tid >> 5, lane = tid & 31;
    int o = lane * 4;
#pragma unroll
    for (int it = 0; it < 4; it++) {
        int e = warp * 4 + it;
        float4 u = *(const float4*)&g_uv[(size_t)s_row[e] * 256 + o];
        float4 v = *(const float4*)&g_uv[(size_t)s_col[e] * 256 + 128 + o];
        float pr = s_pvr[e], pc = s_pvc[e];
        float4 t;
        t.x = fmaxf(u.x + v.x + pr * s_wpr[o]     + pc * s_wpc[o]     + s_bb[o],     0.f);
        t.y = fmaxf(u.y + v.y + pr * s_wpr[o + 1] + pc * s_wpc[o + 1] + s_bb[o + 1], 0.f);
        t.z = fmaxf(u.z + v.z + pr * s_wpr[o + 2] + pc * s_wpc[o + 2] + s_bb[o + 2], 0.f);
        t.w = fmaxf(u.w + v.w + pr * s_wpr[o + 3] + pc * s_wpc[o + 3] + s_bb[o + 3], 0.f);
        *(float4*)&T1[e][o] = t;
    }
    __syncthreads();

    float acc2[2][4];
#pragma unroll
    for (int i = 0; i < 2; i++)
#pragma unroll
        for (int j = 0; j < 4; j++) acc2[i][j] = 0.f;
    const int tx2 = tid & 15, ty2 = tid >> 4;
    for (int kt = 0; kt < 4; kt++) {
        int k0 = kt * 32;
#pragma unroll
        for (int i = 0; i < 2; i++) {
            int idx = tid + 256 * i;
            int k = idx >> 4, c4 = (idx & 15) * 4;
            *(float4*)&Ws[k][c4] = *(const float4*)&w2[(size_t)(k0 + k) * 64 + c4];
        }
        __syncthreads();
#pragma unroll
        for (int kk = 0; kk < 32; kk++) {
            float a0 = T1[ty2 * 2][k0 + kk];
            float a1 = T1[ty2 * 2 + 1][k0 + kk];
            float4 w = *(const float4*)&Ws[kk][tx2 * 4];
            acc2[0][0] += a0 * w.x; acc2[0][1] += a0 * w.y;
            acc2[0][2] += a0 * w.z; acc2[0][3] += a0 * w.w;
            acc2[1][0] += a1 * w.x; acc2[1][1] += a1 * w.y;
            acc2[1][2] += a1 * w.z; acc2[1][3] += a1 * w.w;
        }
        __syncthreads();
    }
#pragma unroll
    for (int i = 0; i < 2; i++) {
        int e = ty2 * 2 + i;
#pragma unroll
        for (int j = 0; j < 4; j++) {
            int oo = tx2 * 4 + j;
            T2[e][oo] = fmaxf(acc2[i][j] + __ldg(&b2[oo]), 0.f);
        }
    }
    __syncthreads();

    if (tid < 128) {
        int e = tid >> 2, oo = tid & 3;
        float s = __ldg(&b3[oo]);
#pragma unroll
        for (int k = 0; k < 64; k++) s += T2[e][k] * __ldg(&w3[k * 4 + oo]);
        int ar = s_atr[e], ac = s_atc[e];
        float pr = s_pvr[e], pc = s_pvc[e];
        bool hal = (ar == 4) || (ar == 5) || (ac == 4) || (ac == 5);
        bool l1 = (pr <= 1.f) || (pc <= 1.f);
        bool l2 = (pr <= 2.f) || (pc <= 2.f);
        float pen = 0.f;
        if (oo >= 1) { if (hal) pen -= 100.f; if (l1) pen -= 50.f; }
        if (oo == 2) { if (l2) pen -= 50.f; }
        out_bl[(size_t)(eb + e) * 4 + oo] = s + pen;
    }
}

// ============================================================
// Chem head (SIMT; fp32 on out_h)
// ============================================================
__global__ __launch_bounds__(256) void k_cp(const float* __restrict__ hfin,
        const float* __restrict__ w1, const float* __restrict__ b1,
        const float* __restrict__ w2, const float* __restrict__ b2,
        float* __restrict__ out_cp)
{
    __shared__ float As[32][36];
    __shared__ float Ws[32][132];
    __shared__ float T1[32][129];
    int tid = threadIdx.x;
    int nb = blockIdx.x * 32;
    float acc[4][4];
#pragma unroll
    for (int i = 0; i < 4; i++)
#pragma unroll
        for (int j = 0; j < 4; j++) acc[i][j] = 0.f;
    const int tx = tid & 31, ty = tid >> 5;
    const int arow = tid >> 3, ac4 = (tid & 7) * 4;
    for (int kt = 0; kt < 8; kt++) {
        int k0 = kt * 32;
        *(float4*)&As[arow][ac4] =
            *(const float4*)&hfin[(size_t)(nb + arow) * HID + k0 + ac4];
#pragma unroll
        for (int i = 0; i < 4; i++) {
            int idx = tid + 256 * i;
            int k = idx >> 5, c4 = (idx & 31) * 4;
            *(float4*)&Ws[k][c4] = *(const float4*)&w1[(size_t)(k0 + k) * 128 + c4];
        }
        __syncthreads();
#pragma unroll
        for (int kk = 0; kk < 32; kk++) {
            float a[4];
#pragma unroll
            for (int i = 0; i < 4; i++) a[i] = As[ty * 4 + i][kk];
            float4 w = *(const float4*)&Ws[kk][tx * 4];
#pragma unroll
            for (int i = 0; i < 4; i++) {
                acc[i][0] += a[i] * w.x; acc[i][1] += a[i] * w.y;
                acc[i][2] += a[i] * w.z; acc[i][3] += a[i] * w.w;
            }
        }
        __syncthreads();
    }
#pragma unroll
    for (int i = 0; i < 4; i++) {
        int e = ty * 4 + i;
#pragma unroll
        for (int j = 0; j < 4; j++) {
            int o = tx * 4 + j;
            T1[e][o] = fmaxf(acc[i][j] + __ldg(&b1[o]), 0.f);
        }
    }
    __syncthreads();

    float acc2[4] = {0.f, 0.f, 0.f, 0.f};
    const int tx2 = tid & 7, ty2 = tid >> 3;
    for (int kt = 0; kt < 4; kt++) {
        int k0 = kt * 32;
        {
            int k = tid >> 3, c4 = (tid & 7) * 4;
            *(float4*)&Ws[k][c4] = *(const float4*)&w2[(size_t)(k0 + k) * 32 + c4];
        }
        __syncthreads();
#pragma unroll
        for (int kk = 0; kk < 32; kk++) {
            float a = T1[ty2][k0 + kk];
            float4 w = *(const float4*)&Ws[kk][tx2 * 4];
            acc2[0] += a * w.x; acc2[1] += a * w.y;
            acc2[2] += a * w.z; acc2[3] += a * w.w;
        }
        __syncthreads();
    }
#pragma unroll
    for (int j = 0; j < 4; j++) {
        int o = tx2 * 4 + j;
        out_cp[(size_t)(nb + ty2) * 32 + o] = acc2[j] + __ldg(&b2[o]);
    }
}

// ============================================================
extern "C" void kernel_launch(void* const* d_in, const int* in_sizes, int n_in,
                              void* d_out, int out_size)
{
    (void)in_sizes; (void)n_in; (void)out_size;
    const float* x         = (const float*)d_in[0];
    const float* edge_attr = (const float*)d_in[1];
    const float* atom_emb  = (const float*)d_in[2];
    const float* bond_emb  = (const float*)d_in[3];
    const float* vp_w1     = (const float*)d_in[4];
    const float* vp_b1     = (const float*)d_in[5];
    const float* vp_w2     = (const float*)d_in[6];
    const float* vp_b2     = (const float*)d_in[7];
    const float* gnn_wself = (const float*)d_in[8];
    const float* gnn_bself = (const float*)d_in[9];
    const float* gnn_wmsg  = (const float*)d_in[10];
    const float* gnn_bmsg  = (const float*)d_in[11];
    const float* bc_w1     = (const float*)d_in[12];
    const float* bc_b1     = (const float*)d_in[13];
    const float* bc_w2     = (const float*)d_in[14];
    const float* bc_b2     = (const float*)d_in[15];
    const float* bc_w3     = (const float*)d_in[16];
    const float* bc_b3     = (const float*)d_in[17];
    const float* cp_w1     = (const float*)d_in[18];
    const float* cp_b1     = (const float*)d_in[19];
    const float* cp_w2     = (const float*)d_in[20];
    const float* cp_b2     = (const float*)d_in[21];
    const int* edge_index  = (const int*)d_in[22];

    float* out      = (float*)d_out;
    float* out_h    = out;                                 // [N,256]
    float* out_cp   = out_h    + (size_t)NN * HID;         // [N,32]
    float* out_vlog = out_cp   + (size_t)NN * 32;          // [N,8]
    float* out_bl   = out_vlog + (size_t)NN * 8;           // [E,4]
    float* out_viol = out_bl   + (size_t)NE * 4;           // [N]

    cudaFuncSetAttribute(k_gemm64, cudaFuncAttributeMaxDynamicSharedMemorySize, SMEM_F16);

    __half *p_h0h, *p_h1h;
    __half2 *p_wmsg, *p_wself, *p_bccat;
    float *p_t, *p_z, *p_uv;
    cudaGetSymbolAddress((void**)&p_h0h,   g_h0h);
    cudaGetSymbolAddress((void**)&p_h1h,   g_h1h);
    cudaGetSymbolAddress((void**)&p_t,     g_t);
    cudaGetSymbolAddress((void**)&p_z,     g_z);
    cudaGetSymbolAddress((void**)&p_uv,    g_uv);
    cudaGetSymbolAddress((void**)&p_wmsg,  g_wmsg_h);
    cudaGetSymbolAddress((void**)&p_wself, g_wself_h);
    cudaGetSymbolAddress((void**)&p_bccat, g_bccat_h);

    const int GB = (NN + 63) / 64;            // 1563 blocks per matrix

    k_prep<<<1303, 256>>>(atom_emb, vp_w1, vp_b1, vp_w2, vp_b2,
                          gnn_wmsg, gnn_bmsg, bond_emb, gnn_wself, bc_w1);
    k_node_init<<<(NN * 32 + 255) / 256, 256>>>(x, atom_emb, out_vlog);
    k_count<<<(NE + 255) / 256, 256>>>(edge_index);
    // layer-0 dual GEMM: t0 = h0@Wmsg0, z0 = h0@Wself0   (captured by ncu)
    k_gemm64<<<2 * GB, 512, SMEM_F16>>>(p_h0h, p_wmsg, p_t, p_wself, p_z, 3, 1);
    k_scan1<<<98, 1024>>>();
    k_scan2<<<1, 128>>>();
    k_scan3<<<98, 1024>>>(out_viol);
    k_scatter<<<(NE + 255) / 256, 256>>>(edge_index, edge_attr);

    // layer 0 aggregate: h1 = agg(z0, t0)
    k_agg<<<NN / 8, 256>>>(p_z, p_t, gnn_bself + 0 * HID, 0, 0, out_h, p_h1h);
    // layer 1
    k_gemm64<<<2 * GB, 512, SMEM_F16>>>(p_h1h, p_wmsg + 32768, p_t,
                                        p_wself + 32768, p_z, 8, 1);
    k_agg<<<NN / 8, 256>>>(p_z, p_t, gnn_bself + 1 * HID, 1, 0, out_h, p_h0h);
    // layer 2 (damped: writes fp32 out_h + fp16 copy for UV GEMM)
    k_gemm64<<<2 * GB, 512, SMEM_F16>>>(p_h0h, p_wmsg + 2 * 32768, p_t,
                                        p_wself + 2 * 32768, p_z, 8, 1);
    k_agg<<<NN / 8, 256>>>(p_z, p_t, gnn_bself + 2 * HID, 2, 1, out_h, p_h1h);

    // bond head precompute: UV = h_final(fp16) @ [W1top|W1bot]
    k_gemm64<<<GB, 512, SMEM_F16>>>(p_h1h, p_bccat, p_uv, nullptr, nullptr, 8, 0);

    k_bc<<<NE / 32, 256>>>(bc_w1, bc_b1, bc_w2, bc_b2, bc_w3, bc_b3,
                           edge_index, out_bl);
    k_cp<<<NN / 32, 256>>>(out_h, cp_w1, cp_b1, cp_w2, cp_b2, out_cp);
}